// round 8
// baseline (speedup 1.0000x reference)
#include <cuda_runtime.h>
#include <cuda_bf16.h>
#include <math.h>

#define HID 256
#define NF  64
#define YS  264   // bf16 row stride, 256-col tiles (conflict-free a-frag LDS)
#define XS  72    // bf16 row stride, 64-col tiles
#define NRMAX 100352
#define MROWS 64  // edges per CTA

// ---------------- device scratch ----------------
__device__ float d_G[NF * NF];
__device__ float d_P[(size_t)NRMAX * HID];  // known_mask @ rm_W1
__device__ float d_rowsum[NRMAX];
__device__ float d_S[HID];  // colsum(rm_W1)
// interleaved fragment tables: uint4 = {hi.x, hi.y, lo.x, lo.y}
__device__ uint4 d_Wf[16 * 32 * 32];   // rc_W
__device__ uint4 d_W2f[16 * 8 * 32];   // rm_W2
__device__ uint4 d_Wrf[4 * 32 * 32];   // rr_W
__device__ uint4 d_W1f[4 * 32 * 32];   // rm_W1 (for P prep)

// ---------------- helpers ----------------
__device__ __forceinline__ float gelu_exact(float x) {
    return 0.5f * x * (1.f + erff(x * 0.7071067811865476f));
}
__device__ __forceinline__ unsigned pack_bf(__nv_bfloat16 a, __nv_bfloat16 b) {
    return (unsigned)__bfloat16_as_ushort(a) | ((unsigned)__bfloat16_as_ushort(b) << 16);
}
__device__ __forceinline__ void split2(float x, float y, unsigned& ph, unsigned& pl) {
    __nv_bfloat16 h0 = __float2bfloat16(x), h1 = __float2bfloat16(y);
    ph = pack_bf(h0, h1);
    pl = pack_bf(__float2bfloat16(x - __bfloat162float(h0)),
                 __float2bfloat16(y - __bfloat162float(h1)));
}
__device__ __forceinline__ void mma_bf16(float c[4], unsigned a0, unsigned a1, unsigned a2,
                                         unsigned a3, unsigned b0, unsigned b1) {
    asm("mma.sync.aligned.m16n8k16.row.col.f32.bf16.bf16.f32 "
        "{%0,%1,%2,%3},{%4,%5,%6,%7},{%8,%9},{%0,%1,%2,%3};"
        : "+f"(c[0]), "+f"(c[1]), "+f"(c[2]), "+f"(c[3])
        : "r"(a0), "r"(a1), "r"(a2), "r"(a3), "r"(b0), "r"(b1));
}
__device__ __forceinline__ void frag_pack(const float* __restrict__ W, int N, int idx,
                                          int NT, uint4* dst) {
    int lane = idx & 31, nt = (idx >> 5) % NT, ks = idx / (NT * 32);
    int n = nt * 8 + (lane >> 2);
    int k0 = ks * 16 + (lane & 3) * 2;
    float w00 = W[k0 * N + n], w01 = W[(k0 + 1) * N + n];
    float w10 = W[(k0 + 8) * N + n], w11 = W[(k0 + 9) * N + n];
    __nv_bfloat16 h00 = __float2bfloat16(w00), h01 = __float2bfloat16(w01);
    __nv_bfloat16 h10 = __float2bfloat16(w10), h11 = __float2bfloat16(w11);
    uint4 v;
    v.x = pack_bf(h00, h01);
    v.y = pack_bf(h10, h11);
    v.z = pack_bf(__float2bfloat16(w00 - __bfloat162float(h00)),
                  __float2bfloat16(w01 - __bfloat162float(h01)));
    v.w = pack_bf(__float2bfloat16(w10 - __bfloat162float(h10)),
                  __float2bfloat16(w11 - __bfloat162float(h11)));
    dst[idx] = v;
}

// ---------------- merged prep kernel (one launch) ----------------
// blocks [0,64): rc_W frags; [64,80): rm_W2; [80,96): rr_W; [96,112): rm_W1;
// block 112: colsum S; blocks [113,129): Gram matrix G.
__global__ void prep_all(const float* __restrict__ rc_W, const float* __restrict__ rm_W2,
                         const float* __restrict__ rr_W, const float* __restrict__ rm_W1,
                         const float* __restrict__ fe) {
    int b = blockIdx.x, tid = threadIdx.x;
    if (b < 64) {
        frag_pack(rc_W, 256, b * 256 + tid, 32, d_Wf);
    } else if (b < 80) {
        frag_pack(rm_W2, 64, (b - 64) * 256 + tid, 8, d_W2f);
    } else if (b < 96) {
        frag_pack(rr_W, 256, (b - 80) * 256 + tid, 32, d_Wrf);
    } else if (b < 112) {
        frag_pack(rm_W1, 256, (b - 96) * 256 + tid, 32, d_W1f);
    } else if (b == 112) {
        float s = 0.f;
#pragma unroll
        for (int k = 0; k < NF; k++) s += rm_W1[k * HID + tid];
        d_S[tid] = s;
    } else {
        int idx = (b - 113) * 256 + tid;
        int i = idx >> 6, j = idx & 63;
        const float4* a = (const float4*)(fe + i * HID);
        const float4* bp = (const float4*)(fe + j * HID);
        float s = 0.f;
#pragma unroll 8
        for (int k = 0; k < HID / 4; k++) {
            float4 x = a[k], y = bp[k];
            s = fmaf(x.x, y.x, fmaf(x.y, y.y, fmaf(x.z, y.z, fmaf(x.w, y.w, s))));
        }
        d_G[i * NF + j] = s;
    }
}

// P = known_mask @ rm_W1 via 2-pass bf16 mma (A binary -> exact); also rowsums.
__global__ void __launch_bounds__(256, 2)
prep_P(const float* __restrict__ km, int nr) {
    __shared__ __align__(16) __nv_bfloat16 kmb[32 * XS];
    const int tid = threadIdx.x, w = tid >> 5, lane = tid & 31;
    const int rbase = blockIdx.x * 32;

    for (int i = tid; i < 32 * 64; i += 256) {
        int row = i >> 6, col = i & 63;
        int gr = rbase + row;
        float v = (gr < nr) ? km[(long)gr * 64 + col] : 0.f;
        kmb[row * XS + col] = __float2bfloat16(v);
    }
#pragma unroll
    for (int r = 0; r < 4; r++) {
        int row = w * 4 + r, gr = rbase + row;
        float v = 0.f;
        if (gr < nr) v = km[(long)gr * 64 + lane] + km[(long)gr * 64 + lane + 32];
#pragma unroll
        for (int o = 16; o > 0; o >>= 1) v += __shfl_xor_sync(0xffffffffu, v, o);
        if (lane == 0 && gr < nr) d_rowsum[gr] = v;
    }
    __syncthreads();

    const int mrow0 = (w & 1) * 16, g0 = (w >> 1) * 8;
    const int arow = mrow0 + (lane >> 2);
    float acc[8][4] = {};
#pragma unroll
    for (int ks = 0; ks < 4; ks++) {
        const int acol = ks * 16 + (lane & 3) * 2;
        unsigned a0 = *(const unsigned*)(kmb + arow * XS + acol);
        unsigned a1 = *(const unsigned*)(kmb + (arow + 8) * XS + acol);
        unsigned a2 = *(const unsigned*)(kmb + arow * XS + acol + 8);
        unsigned a3 = *(const unsigned*)(kmb + (arow + 8) * XS + acol + 8);
        const uint4* Wf = d_W1f + (ks * 32 + g0) * 32 + lane;
#pragma unroll
        for (int j = 0; j < 8; j++) {
            uint4 b = Wf[j * 32];
            mma_bf16(acc[j], a0, a1, a2, a3, b.x, b.y);
            mma_bf16(acc[j], a0, a1, a2, a3, b.z, b.w);
        }
    }
    const int r0 = rbase + arow, r1 = r0 + 8;
#pragma unroll
    for (int j = 0; j < 8; j++) {
        const int col = (g0 + j) * 8 + (lane & 3) * 2;
        if (r0 < nr) *(float2*)(d_P + (long)r0 * HID + col) = make_float2(acc[j][0], acc[j][1]);
        if (r1 < nr) *(float2*)(d_P + (long)r1 * HID + col) = make_float2(acc[j][2], acc[j][3]);
    }
}

// ---------------- fused main kernel: 64 edges per CTA ----------------
#define SMEM_SZ 86528

extern "C" __global__ void __launch_bounds__(256, 2)
arn_fused(const float* __restrict__ known_mask, const int* __restrict__ obs_idx,
          const int* __restrict__ obs_mask_idx, const int* __restrict__ attr_idx,
          const float* __restrict__ obs_embs,
          const float* __restrict__ rm_W1, const float* __restrict__ rm_b1,
          const float* __restrict__ rm_b2, const float* __restrict__ rr_b,
          const float* __restrict__ rc_b, float* __restrict__ out, int E) {
    extern __shared__ __align__(16) char smem[];
    __nv_bfloat16* ybh = (__nv_bfloat16*)smem;
    __nv_bfloat16* ybl = (__nv_bfloat16*)(smem + 33792);
    __nv_bfloat16* xbh = (__nv_bfloat16*)(smem + 67584);
    __nv_bfloat16* xbl = (__nv_bfloat16*)(smem + 76800);
    int* satv = (int*)(smem + 86016);
    int* soiv = (int*)(smem + 86272);

    const int w = threadIdx.x >> 5;
    const int lane = threadIdx.x & 31;
    const long bb = (long)blockIdx.x * MROWS;

    // ---- Phase AB (closed-form softmax + precomputed P): h1 -> ybh/ybl ----
    {
        const int row0 = w * 8;
        const int cc0 = lane * 8;
        const float E1M1 = 1.7182818284590452f;  // e - 1
#pragma unroll 1
        for (int r = 0; r < 8; r++) {
            long e = bb + row0 + r;
            long ec = (e < E) ? e : (long)(E - 1);
            int oi = obs_idx[ec];
            int omi = obs_mask_idx[ec];
            int at = attr_idx[ec];
            if (lane == 0) {
                satv[row0 + r] = at;
                soiv[row0 + r] = oi;
            }
            float t = known_mask[(long)omi * NF + at];  // 0 or 1
            float c = d_rowsum[omi] - t;
            float Z = fmaf(c, E1M1, 64.f);
            float beta = 1.f / Z;
            float dco = E1M1 * beta;  // alpha - beta
            const float* Prow = d_P + (long)omi * HID + cc0;
            float4 p0 = *(const float4*)(Prow);
            float4 p1 = *(const float4*)(Prow + 4);
            if (t != 0.f) {
                const float* w1a = rm_W1 + at * HID + cc0;
                float4 q0 = *(const float4*)(w1a);
                float4 q1 = *(const float4*)(w1a + 4);
                p0.x -= q0.x; p0.y -= q0.y; p0.z -= q0.z; p0.w -= q0.w;
                p1.x -= q1.x; p1.y -= q1.y; p1.z -= q1.z; p1.w -= q1.w;
            }
            float4 s0 = *(const float4*)(d_S + cc0);
            float4 s1 = *(const float4*)(d_S + cc0 + 4);
            float4 b0 = *(const float4*)(rm_b1 + cc0);
            float4 b1v = *(const float4*)(rm_b1 + cc0 + 4);
            float h[8];
            h[0] = gelu_exact(fmaf(beta, s0.x, fmaf(dco, p0.x, b0.x)));
            h[1] = gelu_exact(fmaf(beta, s0.y, fmaf(dco, p0.y, b0.y)));
            h[2] = gelu_exact(fmaf(beta, s0.z, fmaf(dco, p0.z, b0.z)));
            h[3] = gelu_exact(fmaf(beta, s0.w, fmaf(dco, p0.w, b0.w)));
            h[4] = gelu_exact(fmaf(beta, s1.x, fmaf(dco, p1.x, b1v.x)));
            h[5] = gelu_exact(fmaf(beta, s1.y, fmaf(dco, p1.y, b1v.y)));
            h[6] = gelu_exact(fmaf(beta, s1.z, fmaf(dco, p1.z, b1v.z)));
            h[7] = gelu_exact(fmaf(beta, s1.w, fmaf(dco, p1.w, b1v.w)));
            uint4 uh, ul;
            split2(h[0], h[1], uh.x, ul.x);
            split2(h[2], h[3], uh.y, ul.y);
            split2(h[4], h[5], uh.z, ul.z);
            split2(h[6], h[7], uh.w, ul.w);
            *(uint4*)(ybh + (row0 + r) * YS + cc0) = uh;
            *(uint4*)(ybl + (row0 + r) * YS + cc0) = ul;
        }
    }
    __syncthreads();

    const int mrow0 = (w & 3) * 16;      // 4 row groups of 16
    const int cgrp = (w >> 2);           // 2 col groups
    const int arow = mrow0 + (lane >> 2);

    // ---- Phase C: mJ = gelu(h1 @ rm_W2 + b2); x = G[attr] * mJ -> xbh/xbl ----
    {
        const int q0 = cgrp * 4;
        float acc[4][4] = {};
        uint4 bufb[4];
        {
            const uint4* Wf0 = d_W2f + q0 * 32 + lane;
#pragma unroll
            for (int j = 0; j < 4; j++) bufb[j] = Wf0[j * 32];
        }
#pragma unroll 1
        for (int ks = 0; ks < 16; ks++) {
            const int acol = ks * 16 + (lane & 3) * 2;
            unsigned ah0 = *(const unsigned*)(ybh + arow * YS + acol);
            unsigned ah1 = *(const unsigned*)(ybh + (arow + 8) * YS + acol);
            unsigned ah2 = *(const unsigned*)(ybh + arow * YS + acol + 8);
            unsigned ah3 = *(const unsigned*)(ybh + (arow + 8) * YS + acol + 8);
            unsigned al0 = *(const unsigned*)(ybl + arow * YS + acol);
            unsigned al1 = *(const unsigned*)(ybl + (arow + 8) * YS + acol);
            unsigned al2 = *(const unsigned*)(ybl + arow * YS + acol + 8);
            unsigned al3 = *(const unsigned*)(ybl + (arow + 8) * YS + acol + 8);
            uint4 nextb[4];
            if (ks < 15) {
                const uint4* Wfn = d_W2f + ((ks + 1) * 8 + q0) * 32 + lane;
#pragma unroll
                for (int j = 0; j < 4; j++) nextb[j] = Wfn[j * 32];
            }
#pragma unroll
            for (int j = 0; j < 4; j++) {
                mma_bf16(acc[j], ah0, ah1, ah2, ah3, bufb[j].x, bufb[j].y);
                mma_bf16(acc[j], al0, al1, al2, al3, bufb[j].x, bufb[j].y);
                mma_bf16(acc[j], ah0, ah1, ah2, ah3, bufb[j].z, bufb[j].w);
            }
            if (ks < 15) {
#pragma unroll
                for (int j = 0; j < 4; j++) bufb[j] = nextb[j];
            }
        }
        const int at0 = satv[arow], at1 = satv[arow + 8];
#pragma unroll
        for (int j = 0; j < 4; j++) {
            const int col = (q0 + j) * 8 + (lane & 3) * 2;
            float2 b2v = *(const float2*)(rm_b2 + col);
            float2 g0v = *(const float2*)(d_G + at0 * NF + col);
            float2 g1v = *(const float2*)(d_G + at1 * NF + col);
            float x00 = gelu_exact(acc[j][0] + b2v.x) * g0v.x;
            float x01 = gelu_exact(acc[j][1] + b2v.y) * g0v.y;
            float x10 = gelu_exact(acc[j][2] + b2v.x) * g1v.x;
            float x11 = gelu_exact(acc[j][3] + b2v.y) * g1v.y;
            unsigned ph, pl;
            split2(x00, x01, ph, pl);
            *(unsigned*)(xbh + arow * XS + col) = ph;
            *(unsigned*)(xbl + arow * XS + col) = pl;
            split2(x10, x11, ph, pl);
            *(unsigned*)(xbh + (arow + 8) * XS + col) = ph;
            *(unsigned*)(xbl + (arow + 8) * XS + col) = pl;
        }
    }
    __syncthreads();

    // ---- Phase D: a = gelu(x @ rr_W + rr_b); y = obs_h * a -> ybh/ybl ----
    {
        const int oi0 = soiv[arow], oi1 = soiv[arow + 8];
        unsigned axh[4][4], axl[4][4];
#pragma unroll
        for (int ks = 0; ks < 4; ks++) {
            const int acol = ks * 16 + (lane & 3) * 2;
            axh[ks][0] = *(const unsigned*)(xbh + arow * XS + acol);
            axh[ks][1] = *(const unsigned*)(xbh + (arow + 8) * XS + acol);
            axh[ks][2] = *(const unsigned*)(xbh + arow * XS + acol + 8);
            axh[ks][3] = *(const unsigned*)(xbh + (arow + 8) * XS + acol + 8);
            axl[ks][0] = *(const unsigned*)(xbl + arow * XS + acol);
            axl[ks][1] = *(const unsigned*)(xbl + (arow + 8) * XS + acol);
            axl[ks][2] = *(const unsigned*)(xbl + arow * XS + acol + 8);
            axl[ks][3] = *(const unsigned*)(xbl + (arow + 8) * XS + acol + 8);
        }
#pragma unroll 1
        for (int jh = 0; jh < 2; jh++) {
            const int g0 = cgrp * 16 + jh * 8;
            float acc[8][4] = {};
#pragma unroll
            for (int ks = 0; ks < 4; ks++) {
                const uint4* Wf = d_Wrf + (ks * 32 + g0) * 32 + lane;
#pragma unroll
                for (int j = 0; j < 8; j++) {
                    uint4 b = Wf[j * 32];
                    mma_bf16(acc[j], axh[ks][0], axh[ks][1], axh[ks][2], axh[ks][3], b.x, b.y);
                    mma_bf16(acc[j], axl[ks][0], axl[ks][1], axl[ks][2], axl[ks][3], b.x, b.y);
                    mma_bf16(acc[j], axh[ks][0], axh[ks][1], axh[ks][2], axh[ks][3], b.z, b.w);
                }
            }
#pragma unroll
            for (int j = 0; j < 8; j++) {
                const int col = (g0 + j) * 8 + (lane & 3) * 2;
                float2 rb = *(const float2*)(rr_b + col);
                float2 h0 = *(const float2*)(obs_embs + (long)oi0 * HID + col);
                float2 h1 = *(const float2*)(obs_embs + (long)oi1 * HID + col);
                float y00 = gelu_exact(acc[j][0] + rb.x) * h0.x;
                float y01 = gelu_exact(acc[j][1] + rb.y) * h0.y;
                float y10 = gelu_exact(acc[j][2] + rb.x) * h1.x;
                float y11 = gelu_exact(acc[j][3] + rb.y) * h1.y;
                unsigned ph, pl;
                split2(y00, y01, ph, pl);
                *(unsigned*)(ybh + arow * YS + col) = ph;
                *(unsigned*)(ybl + arow * YS + col) = pl;
                split2(y10, y11, ph, pl);
                *(unsigned*)(ybh + (arow + 8) * YS + col) = ph;
                *(unsigned*)(ybl + (arow + 8) * YS + col) = pl;
            }
        }
    }
    __syncthreads();

    // ---- Phase E: out = gelu(y @ rc_W + rc_b) with b-frag prefetch ----
    {
        const long e0 = bb + arow, e1 = e0 + 8;
        const bool w0 = (e0 < (long)E), w1 = (e1 < (long)E);
#pragma unroll 1
        for (int jh = 0; jh < 2; jh++) {
            const int g0 = cgrp * 16 + jh * 8;
            float acc[8][4] = {};
            uint4 bufb[8];
            {
                const uint4* Wf0 = d_Wf + g0 * 32 + lane;
#pragma unroll
                for (int j = 0; j < 8; j++) bufb[j] = Wf0[j * 32];
            }
#pragma unroll 1
            for (int ks = 0; ks < 16; ks++) {
                const int acol = ks * 16 + (lane & 3) * 2;
                unsigned ah0 = *(const unsigned*)(ybh + arow * YS + acol);
                unsigned ah1 = *(const unsigned*)(ybh + (arow + 8) * YS + acol);
                unsigned ah2 = *(const unsigned*)(ybh + arow * YS + acol + 8);
                unsigned ah3 = *(const unsigned*)(ybh + (arow + 8) * YS + acol + 8);
                unsigned al0 = *(const unsigned*)(ybl + arow * YS + acol);
                unsigned al1 = *(const unsigned*)(ybl + (arow + 8) * YS + acol);
                unsigned al2 = *(const unsigned*)(ybl + arow * YS + acol + 8);
                unsigned al3 = *(const unsigned*)(ybl + (arow + 8) * YS + acol + 8);
                uint4 nextb[8];
                if (ks < 15) {
                    const uint4* Wfn = d_Wf + ((ks + 1) * 32 + g0) * 32 + lane;
#pragma unroll
                    for (int j = 0; j < 8; j++) nextb[j] = Wfn[j * 32];
                }
#pragma unroll
                for (int j = 0; j < 8; j++) {
                    mma_bf16(acc[j], ah0, ah1, ah2, ah3, bufb[j].x, bufb[j].y);
                    mma_bf16(acc[j], al0, al1, al2, al3, bufb[j].x, bufb[j].y);
                    mma_bf16(acc[j], ah0, ah1, ah2, ah3, bufb[j].z, bufb[j].w);
                }
                if (ks < 15) {
#pragma unroll
                    for (int j = 0; j < 8; j++) bufb[j] = nextb[j];
                }
            }
#pragma unroll
            for (int j = 0; j < 8; j++) {
                const int col = (g0 + j) * 8 + (lane & 3) * 2;
                float2 bv = *(const float2*)(rc_b + col);
                if (w0) {
                    float2 o;
                    o.x = gelu_exact(acc[j][0] + bv.x);
                    o.y = gelu_exact(acc[j][1] + bv.y);
                    *(float2*)(out + e0 * HID + col) = o;
                }
                if (w1) {
                    float2 o;
                    o.x = gelu_exact(acc[j][2] + bv.x);
                    o.y = gelu_exact(acc[j][3] + bv.y);
                    *(float2*)(out + e1 * HID + col) = o;
                }
            }
        }
    }
}

// ---------------- launch ----------------
extern "C" void kernel_launch(void* const* d_in, const int* in_sizes, int n_in,
                              void* d_out, int out_size) {
    const float* known_mask = (const float*)d_in[0];
    const int* obs_idx = (const int*)d_in[1];
    const int* obs_mask_idx = (const int*)d_in[2];
    const int* attr_idx = (const int*)d_in[3];
    const float* obs_embs = (const float*)d_in[4];
    const float* feature_emb = (const float*)d_in[5];
    const float* rm_W1 = (const float*)d_in[6];
    const float* rm_b1 = (const float*)d_in[7];
    const float* rm_W2 = (const float*)d_in[8];
    const float* rm_b2 = (const float*)d_in[9];
    const float* rr_W = (const float*)d_in[10];
    const float* rr_b = (const float*)d_in[11];
    const float* rc_W = (const float*)d_in[12];
    const float* rc_b = (const float*)d_in[13];
    int E = in_sizes[1];
    int nr = in_sizes[0] / NF;

    static bool attr_set = false;
    if (!attr_set) {
        cudaFuncSetAttribute(arn_fused, cudaFuncAttributeMaxDynamicSharedMemorySize, SMEM_SZ);
        attr_set = true;
    }

    prep_all<<<129, 256>>>(rc_W, rm_W2, rr_W, rm_W1, feature_emb);
    prep_P<<<(nr + 31) / 32, 256>>>(known_mask, nr);
    int grid = (E + MROWS - 1) / MROWS;
    arn_fused<<<grid, 256, SMEM_SZ>>>(known_mask, obs_idx, obs_mask_idx, attr_idx, obs_embs,
                                      rm_W1, rm_b1, rm_b2, rr_b, rc_b, (float*)d_out, E);
}

// round 9
// speedup vs baseline: 1.0308x; 1.0308x over previous
#include <cuda_runtime.h>
#include <cuda_fp16.h>
#include <math.h>

#define HID 256
#define NF  64
#define YS  264   // fp16 row stride, 256-col tiles (conflict-free a-frag LDS)
#define XS  72    // fp16 row stride, 64-col tiles
#define NRMAX 100352
#define MROWS 64  // edges per CTA

// ---------------- device scratch ----------------
__device__ float d_G[NF * NF];
__device__ float d_P[(size_t)NRMAX * HID];  // known_mask @ rm_W1 (EXACT, SIMT)
__device__ float d_rowsum[NRMAX];
__device__ float d_S[HID];  // colsum(rm_W1)
// fp16 weight-split fragment tables: uint4 = {h.b0, h.b1, l.b0, l.b1}
__device__ uint4 d_Wf[16 * 32 * 32];   // rc_W
__device__ uint4 d_W2f[16 * 8 * 32];   // rm_W2
__device__ uint4 d_Wrf[4 * 32 * 32];   // rr_W

// ---------------- helpers ----------------
__device__ __forceinline__ float gelu_exact(float x) {
    return 0.5f * x * (1.f + erff(x * 0.7071067811865476f));
}
__device__ __forceinline__ unsigned pack_h2(float x, float y) {
    __half2 h = __floats2half2_rn(x, y);
    return *(unsigned*)&h;
}
__device__ __forceinline__ void mma_fp16(float c[4], unsigned a0, unsigned a1, unsigned a2,
                                         unsigned a3, unsigned b0, unsigned b1) {
    asm("mma.sync.aligned.m16n8k16.row.col.f32.f16.f16.f32 "
        "{%0,%1,%2,%3},{%4,%5,%6,%7},{%8,%9},{%0,%1,%2,%3};"
        : "+f"(c[0]), "+f"(c[1]), "+f"(c[2]), "+f"(c[3])
        : "r"(a0), "r"(a1), "r"(a2), "r"(a3), "r"(b0), "r"(b1));
}
// Pack W [K x N] row-major into m16n8k16 B-frag order, weights split w = w_h + w_l (fp16).
__device__ __forceinline__ void frag_pack(const float* __restrict__ W, int N, int idx,
                                          int NT, uint4* dst) {
    int lane = idx & 31, nt = (idx >> 5) % NT, ks = idx / (NT * 32);
    int n = nt * 8 + (lane >> 2);
    int k0 = ks * 16 + (lane & 3) * 2;
    float w00 = W[k0 * N + n], w01 = W[(k0 + 1) * N + n];
    float w10 = W[(k0 + 8) * N + n], w11 = W[(k0 + 9) * N + n];
    __half h00 = __float2half_rn(w00), h01 = __float2half_rn(w01);
    __half h10 = __float2half_rn(w10), h11 = __float2half_rn(w11);
    uint4 v;
    v.x = pack_h2(__half2float(h00), 0.f);  // placeholder, repacked below
    // pack hi
    {
        __half2 p0 = __halves2half2(h00, h01);
        __half2 p1 = __halves2half2(h10, h11);
        v.x = *(unsigned*)&p0;
        v.y = *(unsigned*)&p1;
    }
    // pack lo (residual)
    {
        __half2 p0 = __floats2half2_rn(w00 - __half2float(h00), w01 - __half2float(h01));
        __half2 p1 = __floats2half2_rn(w10 - __half2float(h10), w11 - __half2float(h11));
        v.z = *(unsigned*)&p0;
        v.w = *(unsigned*)&p1;
    }
    dst[idx] = v;
}

// ---------------- single merged prep kernel ----------------
// blocks [0,64): rc_W frags; [64,80): rm_W2; [80,96): rr_W; 96: colsum S;
// [97,113): Gram G; [113, 113+ceil(nr/32)): P (exact SIMT) + rowsums.
__global__ void prep_all(const float* __restrict__ rc_W, const float* __restrict__ rm_W2,
                         const float* __restrict__ rr_W, const float* __restrict__ rm_W1,
                         const float* __restrict__ fe, const float* __restrict__ km,
                         int nr) {
    int b = blockIdx.x, tid = threadIdx.x;
    if (b < 64) {
        frag_pack(rc_W, 256, b * 256 + tid, 32, d_Wf);
    } else if (b < 80) {
        frag_pack(rm_W2, 64, (b - 64) * 256 + tid, 8, d_W2f);
    } else if (b < 96) {
        frag_pack(rr_W, 256, (b - 80) * 256 + tid, 32, d_Wrf);
    } else if (b == 96) {
        float s = 0.f;
#pragma unroll
        for (int k = 0; k < NF; k++) s += rm_W1[k * HID + tid];
        d_S[tid] = s;
    } else if (b < 113) {
        int idx = (b - 97) * 256 + tid;
        int i = idx >> 6, j = idx & 63;
        const float4* a = (const float4*)(fe + i * HID);
        const float4* bp = (const float4*)(fe + j * HID);
        float s = 0.f;
#pragma unroll 8
        for (int k = 0; k < HID / 4; k++) {
            float4 x = a[k], y = bp[k];
            s = fmaf(x.x, y.x, fmaf(x.y, y.y, fmaf(x.z, y.z, fmaf(x.w, y.w, s))));
        }
        d_G[i * NF + j] = s;
    } else {
        // P rows: exact conditional accumulation of W1 rows (km binary)
        const int w = tid >> 5, lane = tid & 31;
        const int cc0 = lane * 8;
#pragma unroll 1
        for (int r = 0; r < 4; r++) {
            int gr = (b - 113) * 32 + w * 4 + r;
            int grc = (gr < nr) ? gr : (nr - 1);
            float v0 = km[(long)grc * NF + lane];
            float v1 = km[(long)grc * NF + lane + 32];
            unsigned m0 = __ballot_sync(0xffffffffu, v0 != 0.f);
            unsigned m1 = __ballot_sync(0xffffffffu, v1 != 0.f);
            if (gr >= nr) continue;
            if (lane == 0) d_rowsum[gr] = (float)(__popc(m0) + __popc(m1));
            float acc[8] = {};
#pragma unroll 1
            for (int k = 0; k < NF; k++) {
                unsigned m = (k < 32) ? m0 : m1;
                if ((m >> (k & 31)) & 1u) {
                    float4 wA = *(const float4*)(rm_W1 + k * HID + cc0);
                    float4 wB = *(const float4*)(rm_W1 + k * HID + cc0 + 4);
                    acc[0] += wA.x; acc[1] += wA.y; acc[2] += wA.z; acc[3] += wA.w;
                    acc[4] += wB.x; acc[5] += wB.y; acc[6] += wB.z; acc[7] += wB.w;
                }
            }
            *(float4*)(d_P + (long)gr * HID + cc0) = make_float4(acc[0], acc[1], acc[2], acc[3]);
            *(float4*)(d_P + (long)gr * HID + cc0 + 4) =
                make_float4(acc[4], acc[5], acc[6], acc[7]);
        }
    }
}

// ---------------- fused main kernel: 64 edges per CTA, fp16 2-pass ----------------
// dynamic smem: ybh [64*YS fp16]=33792, xbh @33792 [64*XS fp16]=9216,
// satv @43008 (64 int), soiv @43264 (64 int)
#define SMEM_SZ 43520

extern "C" __global__ void __launch_bounds__(256, 2)
arn_fused(const float* __restrict__ known_mask, const int* __restrict__ obs_idx,
          const int* __restrict__ obs_mask_idx, const int* __restrict__ attr_idx,
          const float* __restrict__ obs_embs,
          const float* __restrict__ rm_W1, const float* __restrict__ rm_b1,
          const float* __restrict__ rm_b2, const float* __restrict__ rr_b,
          const float* __restrict__ rc_b, float* __restrict__ out, int E) {
    extern __shared__ __align__(16) char smem[];
    __half* ybh = (__half*)smem;
    __half* xbh = (__half*)(smem + 33792);
    int* satv = (int*)(smem + 43008);
    int* soiv = (int*)(smem + 43264);

    const int w = threadIdx.x >> 5;
    const int lane = threadIdx.x & 31;
    const long bb = (long)blockIdx.x * MROWS;

    // ---- Phase AB (closed-form softmax + exact P): h1 -> ybh (fp16) ----
    {
        const int row0 = w * 8;
        const int cc0 = lane * 8;
        const float E1M1 = 1.7182818284590452f;  // e - 1
#pragma unroll 1
        for (int r = 0; r < 8; r++) {
            long e = bb + row0 + r;
            long ec = (e < E) ? e : (long)(E - 1);
            int oi = obs_idx[ec];
            int omi = obs_mask_idx[ec];
            int at = attr_idx[ec];
            if (lane == 0) {
                satv[row0 + r] = at;
                soiv[row0 + r] = oi;
            }
            float t = known_mask[(long)omi * NF + at];  // 0 or 1
            float c = d_rowsum[omi] - t;
            float Z = fmaf(c, E1M1, 64.f);
            float beta = 1.f / Z;
            float dco = E1M1 * beta;  // alpha - beta
            const float* Prow = d_P + (long)omi * HID + cc0;
            float4 p0 = *(const float4*)(Prow);
            float4 p1 = *(const float4*)(Prow + 4);
            if (t != 0.f) {
                const float* w1a = rm_W1 + at * HID + cc0;
                float4 q0 = *(const float4*)(w1a);
                float4 q1 = *(const float4*)(w1a + 4);
                p0.x -= q0.x; p0.y -= q0.y; p0.z -= q0.z; p0.w -= q0.w;
                p1.x -= q1.x; p1.y -= q1.y; p1.z -= q1.z; p1.w -= q1.w;
            }
            float4 s0 = *(const float4*)(d_S + cc0);
            float4 s1 = *(const float4*)(d_S + cc0 + 4);
            float4 b0 = *(const float4*)(rm_b1 + cc0);
            float4 b1v = *(const float4*)(rm_b1 + cc0 + 4);
            float h[8];
            h[0] = gelu_exact(fmaf(beta, s0.x, fmaf(dco, p0.x, b0.x)));
            h[1] = gelu_exact(fmaf(beta, s0.y, fmaf(dco, p0.y, b0.y)));
            h[2] = gelu_exact(fmaf(beta, s0.z, fmaf(dco, p0.z, b0.z)));
            h[3] = gelu_exact(fmaf(beta, s0.w, fmaf(dco, p0.w, b0.w)));
            h[4] = gelu_exact(fmaf(beta, s1.x, fmaf(dco, p1.x, b1v.x)));
            h[5] = gelu_exact(fmaf(beta, s1.y, fmaf(dco, p1.y, b1v.y)));
            h[6] = gelu_exact(fmaf(beta, s1.z, fmaf(dco, p1.z, b1v.z)));
            h[7] = gelu_exact(fmaf(beta, s1.w, fmaf(dco, p1.w, b1v.w)));
            uint4 uh;
            uh.x = pack_h2(h[0], h[1]);
            uh.y = pack_h2(h[2], h[3]);
            uh.z = pack_h2(h[4], h[5]);
            uh.w = pack_h2(h[6], h[7]);
            *(uint4*)(ybh + (row0 + r) * YS + cc0) = uh;
        }
    }
    __syncthreads();

    const int mrow0 = (w & 3) * 16;  // 4 row groups of 16
    const int cgrp = (w >> 2);       // 2 col groups
    const int arow = mrow0 + (lane >> 2);

    // ---- Phase C: mJ = gelu(h1 @ rm_W2 + b2); x = G[attr] * mJ -> xbh ----
    {
        const int q0 = cgrp * 4;
        float acc[4][4] = {};
#pragma unroll 1
        for (int ks = 0; ks < 16; ks++) {
            const int acol = ks * 16 + (lane & 3) * 2;
            unsigned a0 = *(const unsigned*)(ybh + arow * YS + acol);
            unsigned a1 = *(const unsigned*)(ybh + (arow + 8) * YS + acol);
            unsigned a2 = *(const unsigned*)(ybh + arow * YS + acol + 8);
            unsigned a3 = *(const unsigned*)(ybh + (arow + 8) * YS + acol + 8);
            const uint4* Wf = d_W2f + (ks * 8 + q0) * 32 + lane;
#pragma unroll
            for (int j = 0; j < 4; j++) {
                uint4 bv = Wf[j * 32];
                mma_fp16(acc[j], a0, a1, a2, a3, bv.x, bv.y);
                mma_fp16(acc[j], a0, a1, a2, a3, bv.z, bv.w);
            }
        }
        const int at0 = satv[arow], at1 = satv[arow + 8];
#pragma unroll
        for (int j = 0; j < 4; j++) {
            const int col = (q0 + j) * 8 + (lane & 3) * 2;
            float2 b2v = *(const float2*)(rm_b2 + col);
            float2 g0v = *(const float2*)(d_G + at0 * NF + col);
            float2 g1v = *(const float2*)(d_G + at1 * NF + col);
            float x00 = gelu_exact(acc[j][0] + b2v.x) * g0v.x;
            float x01 = gelu_exact(acc[j][1] + b2v.y) * g0v.y;
            float x10 = gelu_exact(acc[j][2] + b2v.x) * g1v.x;
            float x11 = gelu_exact(acc[j][3] + b2v.y) * g1v.y;
            *(unsigned*)(xbh + arow * XS + col) = pack_h2(x00, x01);
            *(unsigned*)(xbh + (arow + 8) * XS + col) = pack_h2(x10, x11);
        }
    }
    __syncthreads();

    // ---- Phase D: a = gelu(x @ rr_W + rr_b); y = obs_h * a -> ybh ----
    {
        const int oi0 = soiv[arow], oi1 = soiv[arow + 8];
        unsigned ax[4][4];
#pragma unroll
        for (int ks = 0; ks < 4; ks++) {
            const int acol = ks * 16 + (lane & 3) * 2;
            ax[ks][0] = *(const unsigned*)(xbh + arow * XS + acol);
            ax[ks][1] = *(const unsigned*)(xbh + (arow + 8) * XS + acol);
            ax[ks][2] = *(const unsigned*)(xbh + arow * XS + acol + 8);
            ax[ks][3] = *(const unsigned*)(xbh + (arow + 8) * XS + acol + 8);
        }
#pragma unroll 1
        for (int jh = 0; jh < 2; jh++) {
            const int g0 = cgrp * 16 + jh * 8;
            float acc[8][4] = {};
#pragma unroll
            for (int ks = 0; ks < 4; ks++) {
                const uint4* Wf = d_Wrf + (ks * 32 + g0) * 32 + lane;
#pragma unroll
                for (int j = 0; j < 8; j++) {
                    uint4 bv = Wf[j * 32];
                    mma_fp16(acc[j], ax[ks][0], ax[ks][1], ax[ks][2], ax[ks][3], bv.x, bv.y);
                    mma_fp16(acc[j], ax[ks][0], ax[ks][1], ax[ks][2], ax[ks][3], bv.z, bv.w);
                }
            }
#pragma unroll
            for (int j = 0; j < 8; j++) {
                const int col = (g0 + j) * 8 + (lane & 3) * 2;
                float2 rb = *(const float2*)(rr_b + col);
                float2 h0 = *(const float2*)(obs_embs + (long)oi0 * HID + col);
                float2 h1 = *(const float2*)(obs_embs + (long)oi1 * HID + col);
                float y00 = gelu_exact(acc[j][0] + rb.x) * h0.x;
                float y01 = gelu_exact(acc[j][1] + rb.y) * h0.y;
                float y10 = gelu_exact(acc[j][2] + rb.x) * h1.x;
                float y11 = gelu_exact(acc[j][3] + rb.y) * h1.y;
                *(unsigned*)(ybh + arow * YS + col) = pack_h2(y00, y01);
                *(unsigned*)(ybh + (arow + 8) * YS + col) = pack_h2(y10, y11);
            }
        }
    }
    __syncthreads();

    // ---- Phase E: out = gelu(y @ rc_W + rc_b) ----
    {
        const long e0 = bb + arow, e1 = e0 + 8;
        const bool w0 = (e0 < (long)E), w1 = (e1 < (long)E);
#pragma unroll 1
        for (int jh = 0; jh < 2; jh++) {
            const int g0 = cgrp * 16 + jh * 8;
            float acc[8][4] = {};
#pragma unroll 1
            for (int ks = 0; ks < 16; ks++) {
                const int acol = ks * 16 + (lane & 3) * 2;
                unsigned a0 = *(const unsigned*)(ybh + arow * YS + acol);
                unsigned a1 = *(const unsigned*)(ybh + (arow + 8) * YS + acol);
                unsigned a2 = *(const unsigned*)(ybh + arow * YS + acol + 8);
                unsigned a3 = *(const unsigned*)(ybh + (arow + 8) * YS + acol + 8);
                const uint4* Wf = d_Wf + (ks * 32 + g0) * 32 + lane;
#pragma unroll
                for (int j = 0; j < 8; j++) {
                    uint4 bv = Wf[j * 32];
                    mma_fp16(acc[j], a0, a1, a2, a3, bv.x, bv.y);
                    mma_fp16(acc[j], a0, a1, a2, a3, bv.z, bv.w);
                }
            }
#pragma unroll
            for (int j = 0; j < 8; j++) {
                const int col = (g0 + j) * 8 + (lane & 3) * 2;
                float2 bv = *(const float2*)(rc_b + col);
                if (w0) {
                    float2 o;
                    o.x = gelu_exact(acc[j][0] + bv.x);
                    o.y = gelu_exact(acc[j][1] + bv.y);
                    *(float2*)(out + e0 * HID + col) = o;
                }
                if (w1) {
                    float2 o;
                    o.x = gelu_exact(acc[j][2] + bv.x);
                    o.y = gelu_exact(acc[j][3] + bv.y);
                    *(float2*)(out + e1 * HID + col) = o;
                }
            }
        }
    }
}

// ---------------- launch ----------------
extern "C" void kernel_launch(void* const* d_in, const int* in_sizes, int n_in,
                              void* d_out, int out_size) {
    const float* known_mask = (const float*)d_in[0];
    const int* obs_idx = (const int*)d_in[1];
    const int* obs_mask_idx = (const int*)d_in[2];
    const int* attr_idx = (const int*)d_in[3];
    const float* obs_embs = (const float*)d_in[4];
    const float* feature_emb = (const float*)d_in[5];
    const float* rm_W1 = (const float*)d_in[6];
    const float* rm_b1 = (const float*)d_in[7];
    const float* rm_W2 = (const float*)d_in[8];
    const float* rm_b2 = (const float*)d_in[9];
    const float* rr_W = (const float*)d_in[10];
    const float* rr_b = (const float*)d_in[11];
    const float* rc_W = (const float*)d_in[12];
    const float* rc_b = (const float*)d_in[13];
    int E = in_sizes[1];
    int nr = in_sizes[0] / NF;

    static bool attr_set = false;
    if (!attr_set) {
        cudaFuncSetAttribute(arn_fused, cudaFuncAttributeMaxDynamicSharedMemorySize, SMEM_SZ);
        attr_set = true;
    }

    int np = (nr + 31) / 32;
    prep_all<<<113 + np, 256>>>(rc_W, rm_W2, rr_W, rm_W1, feature_emb, known_mask, nr);
    int grid = (E + MROWS - 1) / MROWS;
    arn_fused<<<grid, 256, SMEM_SZ>>>(known_mask, obs_idx, obs_mask_idx, attr_idx, obs_embs,
                                      rm_W1, rm_b1, rm_b2, rr_b, rc_b, (float*)d_out, E);
}

// round 10
// speedup vs baseline: 1.0331x; 1.0022x over previous
#include <cuda_runtime.h>
#include <cuda_fp16.h>
#include <math.h>

#define HID 256
#define NF  64
#define YS  264   // fp16 row stride, 256-col tiles
#define XS  72    // fp16 row stride, 64-col tiles
#define NRMAX 100352
#define MROWS 64  // edges per CTA

// ---------------- device scratch ----------------
__device__ float d_G[NF * NF];
__device__ float d_P[(size_t)NRMAX * HID];  // known_mask @ rm_W1 (EXACT)
__device__ float d_rowsum[NRMAX];
__device__ float d_S[HID];  // colsum(rm_W1)
// fp16 fragment tables: uint2 = {b0, b1}
__device__ uint2 d_Wf[16 * 32 * 32];   // rc_W  (128KB, L1-resident)
__device__ uint2 d_W2f[16 * 8 * 32];   // rm_W2
__device__ uint2 d_Wrf[4 * 32 * 32];   // rr_W

// ---------------- helpers ----------------
__device__ __forceinline__ float gelu_exact(float x) {
    return 0.5f * x * (1.f + erff(x * 0.7071067811865476f));
}
__device__ __forceinline__ unsigned pack_h2(float x, float y) {
    __half2 h = __floats2half2_rn(x, y);
    return *(unsigned*)&h;
}
__device__ __forceinline__ void mma_fp16(float c[4], unsigned a0, unsigned a1, unsigned a2,
                                         unsigned a3, unsigned b0, unsigned b1) {
    asm("mma.sync.aligned.m16n8k16.row.col.f32.f16.f16.f32 "
        "{%0,%1,%2,%3},{%4,%5,%6,%7},{%8,%9},{%0,%1,%2,%3};"
        : "+f"(c[0]), "+f"(c[1]), "+f"(c[2]), "+f"(c[3])
        : "r"(a0), "r"(a1), "r"(a2), "r"(a3), "r"(b0), "r"(b1));
}
__device__ __forceinline__ void ldsm4(unsigned& a0, unsigned& a1, unsigned& a2, unsigned& a3,
                                      unsigned addr) {
    asm volatile("ldmatrix.sync.aligned.m8n8.x4.shared.b16 {%0,%1,%2,%3},[%4];"
                 : "=r"(a0), "=r"(a1), "=r"(a2), "=r"(a3)
                 : "r"(addr));
}
// Pack W [K x N] row-major into m16n8k16 B-frag order, fp16.
__device__ __forceinline__ void frag_pack(const float* __restrict__ W, int N, int idx,
                                          int NT, uint2* dst) {
    int lane = idx & 31, nt = (idx >> 5) % NT, ks = idx / (NT * 32);
    int n = nt * 8 + (lane >> 2);
    int k0 = ks * 16 + (lane & 3) * 2;
    uint2 v;
    v.x = pack_h2(W[k0 * N + n], W[(k0 + 1) * N + n]);
    v.y = pack_h2(W[(k0 + 8) * N + n], W[(k0 + 9) * N + n]);
    dst[idx] = v;
}

// ---------------- single merged prep kernel ----------------
// blocks [0,64): rc_W frags; [64,80): rm_W2; [80,96): rr_W; 96: colsum S;
// [97,113): Gram G; [113, 113+ceil(nr/32)): P (exact, smem-staged W1) + rowsums.
__global__ void prep_all(const float* __restrict__ rc_W, const float* __restrict__ rm_W2,
                         const float* __restrict__ rr_W, const float* __restrict__ rm_W1,
                         const float* __restrict__ fe, const float* __restrict__ km,
                         int nr) {
    extern __shared__ __align__(16) float sW[];  // 64KB: rm_W1 staged
    int b = blockIdx.x, tid = threadIdx.x;
    if (b < 64) {
        frag_pack(rc_W, 256, b * 256 + tid, 32, d_Wf);
    } else if (b < 80) {
        frag_pack(rm_W2, 64, (b - 64) * 256 + tid, 8, d_W2f);
    } else if (b < 96) {
        frag_pack(rr_W, 256, (b - 80) * 256 + tid, 32, d_Wrf);
    } else if (b == 96) {
        float s = 0.f;
#pragma unroll
        for (int k = 0; k < NF; k++) s += rm_W1[k * HID + tid];
        d_S[tid] = s;
    } else if (b < 113) {
        int idx = (b - 97) * 256 + tid;
        int i = idx >> 6, j = idx & 63;
        const float4* a = (const float4*)(fe + i * HID);
        const float4* bp = (const float4*)(fe + j * HID);
        float s = 0.f;
#pragma unroll 8
        for (int k = 0; k < HID / 4; k++) {
            float4 x = a[k], y = bp[k];
            s = fmaf(x.x, y.x, fmaf(x.y, y.y, fmaf(x.z, y.z, fmaf(x.w, y.w, s))));
        }
        d_G[i * NF + j] = s;
    } else {
        // stage rm_W1 (64KB) in smem
        for (int i = tid; i < NF * HID / 4; i += 256)
            ((float4*)sW)[i] = ((const float4*)rm_W1)[i];
        __syncthreads();
        const int w = tid >> 5, lane = tid & 31;
        const int cc0 = lane * 8;
#pragma unroll 1
        for (int r = 0; r < 4; r++) {
            int gr = (b - 113) * 32 + w * 4 + r;
            int grc = (gr < nr) ? gr : (nr - 1);
            float v0 = km[(long)grc * NF + lane];
            float v1 = km[(long)grc * NF + lane + 32];
            unsigned m0 = __ballot_sync(0xffffffffu, v0 != 0.f);
            unsigned m1 = __ballot_sync(0xffffffffu, v1 != 0.f);
            if (gr >= nr) continue;
            if (lane == 0) d_rowsum[gr] = (float)(__popc(m0) + __popc(m1));
            unsigned long long mask = (unsigned long long)m0 | ((unsigned long long)m1 << 32);
            float acc[8] = {};
#pragma unroll 8
            for (int k = 0; k < NF; k++) {
                float sel = ((mask >> k) & 1ull) ? 1.f : 0.f;
                float4 wA = *(const float4*)(sW + k * HID + cc0);
                float4 wB = *(const float4*)(sW + k * HID + cc0 + 4);
                acc[0] = fmaf(sel, wA.x, acc[0]);
                acc[1] = fmaf(sel, wA.y, acc[1]);
                acc[2] = fmaf(sel, wA.z, acc[2]);
                acc[3] = fmaf(sel, wA.w, acc[3]);
                acc[4] = fmaf(sel, wB.x, acc[4]);
                acc[5] = fmaf(sel, wB.y, acc[5]);
                acc[6] = fmaf(sel, wB.z, acc[6]);
                acc[7] = fmaf(sel, wB.w, acc[7]);
            }
            *(float4*)(d_P + (long)gr * HID + cc0) = make_float4(acc[0], acc[1], acc[2], acc[3]);
            *(float4*)(d_P + (long)gr * HID + cc0 + 4) =
                make_float4(acc[4], acc[5], acc[6], acc[7]);
        }
    }
}

// ---------------- fused main kernel: 64 edges per CTA, fp16 1-pass ----------------
// dynamic smem: ybh [64*YS fp16]=33792, xbh @33792 [64*XS fp16]=9216,
// satv @43008 (64 int), soiv @43264 (64 int)
#define SMEM_SZ 43520

extern "C" __global__ void __launch_bounds__(256, 2)
arn_fused(const float* __restrict__ known_mask, const int* __restrict__ obs_idx,
          const int* __restrict__ obs_mask_idx, const int* __restrict__ attr_idx,
          const float* __restrict__ obs_embs,
          const float* __restrict__ rm_W1, const float* __restrict__ rm_b1,
          const float* __restrict__ rm_b2, const float* __restrict__ rr_b,
          const float* __restrict__ rc_b, float* __restrict__ out, int E) {
    extern __shared__ __align__(16) char smem[];
    __half* ybh = (__half*)smem;
    __half* xbh = (__half*)(smem + 33792);
    int* satv = (int*)(smem + 43008);
    int* soiv = (int*)(smem + 43264);

    const int w = threadIdx.x >> 5;
    const int lane = threadIdx.x & 31;
    const long bb = (long)blockIdx.x * MROWS;

    // ---- Phase AB (closed-form softmax + exact P): h1 -> ybh (fp16) ----
    {
        const int row0 = w * 8;
        const int cc0 = lane * 8;
        const float E1M1 = 1.7182818284590452f;  // e - 1
#pragma unroll 1
        for (int r = 0; r < 8; r++) {
            long e = bb + row0 + r;
            long ec = (e < E) ? e : (long)(E - 1);
            int oi = obs_idx[ec];
            int omi = obs_mask_idx[ec];
            int at = attr_idx[ec];
            if (lane == 0) {
                satv[row0 + r] = at;
                soiv[row0 + r] = oi;
            }
            float t = known_mask[(long)omi * NF + at];  // 0 or 1
            float c = d_rowsum[omi] - t;
            float Z = fmaf(c, E1M1, 64.f);
            float beta = 1.f / Z;
            float dco = E1M1 * beta;  // alpha - beta
            const float* Prow = d_P + (long)omi * HID + cc0;
            float4 p0 = *(const float4*)(Prow);
            float4 p1 = *(const float4*)(Prow + 4);
            if (t != 0.f) {
                const float* w1a = rm_W1 + at * HID + cc0;
                float4 q0 = *(const float4*)(w1a);
                float4 q1 = *(const float4*)(w1a + 4);
                p0.x -= q0.x; p0.y -= q0.y; p0.z -= q0.z; p0.w -= q0.w;
                p1.x -= q1.x; p1.y -= q1.y; p1.z -= q1.z; p1.w -= q1.w;
            }
            float4 s0 = *(const float4*)(d_S + cc0);
            float4 s1 = *(const float4*)(d_S + cc0 + 4);
            float4 b0 = *(const float4*)(rm_b1 + cc0);
            float4 b1v = *(const float4*)(rm_b1 + cc0 + 4);
            float h[8];
            h[0] = gelu_exact(fmaf(beta, s0.x, fmaf(dco, p0.x, b0.x)));
            h[1] = gelu_exact(fmaf(beta, s0.y, fmaf(dco, p0.y, b0.y)));
            h[2] = gelu_exact(fmaf(beta, s0.z, fmaf(dco, p0.z, b0.z)));
            h[3] = gelu_exact(fmaf(beta, s0.w, fmaf(dco, p0.w, b0.w)));
            h[4] = gelu_exact(fmaf(beta, s1.x, fmaf(dco, p1.x, b1v.x)));
            h[5] = gelu_exact(fmaf(beta, s1.y, fmaf(dco, p1.y, b1v.y)));
            h[6] = gelu_exact(fmaf(beta, s1.z, fmaf(dco, p1.z, b1v.z)));
            h[7] = gelu_exact(fmaf(beta, s1.w, fmaf(dco, p1.w, b1v.w)));
            uint4 uh;
            uh.x = pack_h2(h[0], h[1]);
            uh.y = pack_h2(h[2], h[3]);
            uh.z = pack_h2(h[4], h[5]);
            uh.w = pack_h2(h[6], h[7]);
            *(uint4*)(ybh + (row0 + r) * YS + cc0) = uh;
        }
    }
    __syncthreads();

    const int mrow0 = (w & 3) * 16;  // 4 row groups of 16
    const int cgrp = (w >> 2);       // 2 col groups
    const int arow = mrow0 + (lane >> 2);

    // ldmatrix lane addressing (tiles: m0-7/k0, m8-15/k0, m0-7/k8, m8-15/k8)
    const int lrow = mrow0 + (lane & 7) + ((lane >> 3) & 1) * 8;
    const int lcol = (lane >> 4) * 8;
    const unsigned ybh_s = (unsigned)__cvta_generic_to_shared(ybh);
    const unsigned xbh_s = (unsigned)__cvta_generic_to_shared(xbh);
    const unsigned yaddr0 = ybh_s + (lrow * YS + lcol) * 2;
    const unsigned xaddr0 = xbh_s + (lrow * XS + lcol) * 2;

    // ---- Phase C: mJ = gelu(h1 @ rm_W2 + b2); x = G[attr] * mJ -> xbh ----
    {
        const int q0 = cgrp * 4;
        float acc[4][4] = {};
#pragma unroll 1
        for (int ks = 0; ks < 16; ks++) {
            unsigned a0, a1, a2, a3;
            ldsm4(a0, a1, a2, a3, yaddr0 + ks * 32);
            const uint2* Wf = d_W2f + (ks * 8 + q0) * 32 + lane;
#pragma unroll
            for (int j = 0; j < 4; j++) {
                uint2 bv = Wf[j * 32];
                mma_fp16(acc[j], a0, a1, a2, a3, bv.x, bv.y);
            }
        }
        const int at0 = satv[arow], at1 = satv[arow + 8];
#pragma unroll
        for (int j = 0; j < 4; j++) {
            const int col = (q0 + j) * 8 + (lane & 3) * 2;
            float2 b2v = *(const float2*)(rm_b2 + col);
            float2 g0v = *(const float2*)(d_G + at0 * NF + col);
            float2 g1v = *(const float2*)(d_G + at1 * NF + col);
            *(unsigned*)(xbh + arow * XS + col) =
                pack_h2(gelu_exact(acc[j][0] + b2v.x) * g0v.x,
                        gelu_exact(acc[j][1] + b2v.y) * g0v.y);
            *(unsigned*)(xbh + (arow + 8) * XS + col) =
                pack_h2(gelu_exact(acc[j][2] + b2v.x) * g1v.x,
                        gelu_exact(acc[j][3] + b2v.y) * g1v.y);
        }
    }
    __syncthreads();

    // ---- Phase D: a = gelu(x @ rr_W + rr_b); y = obs_h * a -> ybh ----
    {
        const int oi0 = soiv[arow], oi1 = soiv[arow + 8];
        float acc[16][4] = {};
#pragma unroll
        for (int ks = 0; ks < 4; ks++) {
            unsigned a0, a1, a2, a3;
            ldsm4(a0, a1, a2, a3, xaddr0 + ks * 32);
            const uint2* Wf = d_Wrf + (ks * 32 + cgrp * 16) * 32 + lane;
#pragma unroll
            for (int j = 0; j < 16; j++) {
                uint2 bv = Wf[j * 32];
                mma_fp16(acc[j], a0, a1, a2, a3, bv.x, bv.y);
            }
        }
#pragma unroll
        for (int j = 0; j < 16; j++) {
            const int col = (cgrp * 16 + j) * 8 + (lane & 3) * 2;
            float2 rb = *(const float2*)(rr_b + col);
            float2 h0 = *(const float2*)(obs_embs + (long)oi0 * HID + col);
            float2 h1 = *(const float2*)(obs_embs + (long)oi1 * HID + col);
            *(unsigned*)(ybh + arow * YS + col) =
                pack_h2(gelu_exact(acc[j][0] + rb.x) * h0.x,
                        gelu_exact(acc[j][1] + rb.y) * h0.y);
            *(unsigned*)(ybh + (arow + 8) * YS + col) =
                pack_h2(gelu_exact(acc[j][2] + rb.x) * h1.x,
                        gelu_exact(acc[j][3] + rb.y) * h1.y);
        }
    }
    __syncthreads();

    // ---- Phase E: out = gelu(y @ rc_W + rc_b) ----
    {
        const long e0 = bb + arow, e1 = e0 + 8;
        const bool w0 = (e0 < (long)E), w1 = (e1 < (long)E);
        float acc[16][4] = {};
#pragma unroll 1
        for (int ks = 0; ks < 16; ks++) {
            unsigned a0, a1, a2, a3;
            ldsm4(a0, a1, a2, a3, yaddr0 + ks * 32);
            const uint2* Wf = d_Wf + (ks * 32 + cgrp * 16) * 32 + lane;
#pragma unroll
            for (int j = 0; j < 16; j++) {
                uint2 bv = Wf[j * 32];
                mma_fp16(acc[j], a0, a1, a2, a3, bv.x, bv.y);
            }
        }
#pragma unroll
        for (int j = 0; j < 16; j++) {
            const int col = (cgrp * 16 + j) * 8 + (lane & 3) * 2;
            float2 bv = *(const float2*)(rc_b + col);
            if (w0) {
                float2 o;
                o.x = gelu_exact(acc[j][0] + bv.x);
                o.y = gelu_exact(acc[j][1] + bv.y);
                *(float2*)(out + e0 * HID + col) = o;
            }
            if (w1) {
                float2 o;
                o.x = gelu_exact(acc[j][2] + bv.x);
                o.y = gelu_exact(acc[j][3] + bv.y);
                *(float2*)(out + e1 * HID + col) = o;
            }
        }
    }
}

// ---------------- launch ----------------
extern "C" void kernel_launch(void* const* d_in, const int* in_sizes, int n_in,
                              void* d_out, int out_size) {
    const float* known_mask = (const float*)d_in[0];
    const int* obs_idx = (const int*)d_in[1];
    const int* obs_mask_idx = (const int*)d_in[2];
    const int* attr_idx = (const int*)d_in[3];
    const float* obs_embs = (const float*)d_in[4];
    const float* feature_emb = (const float*)d_in[5];
    const float* rm_W1 = (const float*)d_in[6];
    const float* rm_b1 = (const float*)d_in[7];
    const float* rm_W2 = (const float*)d_in[8];
    const float* rm_b2 = (const float*)d_in[9];
    const float* rr_W = (const float*)d_in[10];
    const float* rr_b = (const float*)d_in[11];
    const float* rc_W = (const float*)d_in[12];
    const float* rc_b = (const float*)d_in[13];
    int E = in_sizes[1];
    int nr = in_sizes[0] / NF;

    static bool attr_set = false;
    if (!attr_set) {
        cudaFuncSetAttribute(arn_fused, cudaFuncAttributeMaxDynamicSharedMemorySize, SMEM_SZ);
        cudaFuncSetAttribute(prep_all, cudaFuncAttributeMaxDynamicSharedMemorySize, 65536);
        attr_set = true;
    }

    int np = (nr + 31) / 32;
    prep_all<<<113 + np, 256, 65536>>>(rc_W, rm_W2, rr_W, rm_W1, feature_emb, known_mask, nr);
    int grid = (E + MROWS - 1) / MROWS;
    arn_fused<<<grid, 256, SMEM_SZ>>>(known_mask, obs_idx, obs_mask_idx, attr_idx, obs_embs,
                                      rm_W1, rm_b1, rm_b2, rr_b, rc_b, (float*)d_out, E);
}

// round 11
// speedup vs baseline: 1.6797x; 1.6258x over previous
#include <cuda_runtime.h>
#include <cuda_fp16.h>
#include <math.h>

#define HID 256
#define NF  64
#define YS  264   // fp16 row stride, 256-col tiles
#define XS  72    // fp16 row stride, 64-col tiles
#define NRMAX 100352
#define MROWS 64  // edges per CTA

// ---------------- device scratch ----------------
__device__ float d_G[NF * NF];
__device__ float d_P[(size_t)NRMAX * HID];  // known_mask @ rm_W1 (near-exact)
__device__ float d_rowsum[NRMAX];
__device__ float d_S[HID];  // colsum(rm_W1)
// fp16 fragment tables
__device__ uint2 d_Wf[16 * 32 * 32];   // rc_W  (128KB, L1-resident)
__device__ uint2 d_W2f[16 * 8 * 32];   // rm_W2
__device__ uint2 d_Wrf[4 * 32 * 32];   // rr_W
__device__ uint4 d_W1f[4 * 32 * 32];   // rm_W1 2-pass {h0,h1,l0,l1} (for P prep)

// ---------------- helpers ----------------
__device__ __forceinline__ float gelu_exact(float x) {
    return 0.5f * x * (1.f + erff(x * 0.7071067811865476f));
}
__device__ __forceinline__ float gelu_fast(float x) {
    float inner = 0.7978845608028654f * x * fmaf(0.044715f, x * x, 1.f);
    float t;
    asm("tanh.approx.f32 %0,%1;" : "=f"(t) : "f"(inner));
    return 0.5f * x * (1.f + t);
}
__device__ __forceinline__ unsigned pack_h2(float x, float y) {
    __half2 h = __floats2half2_rn(x, y);
    return *(unsigned*)&h;
}
__device__ __forceinline__ void mma_fp16(float c[4], unsigned a0, unsigned a1, unsigned a2,
                                         unsigned a3, unsigned b0, unsigned b1) {
    asm("mma.sync.aligned.m16n8k16.row.col.f32.f16.f16.f32 "
        "{%0,%1,%2,%3},{%4,%5,%6,%7},{%8,%9},{%0,%1,%2,%3};"
        : "+f"(c[0]), "+f"(c[1]), "+f"(c[2]), "+f"(c[3])
        : "r"(a0), "r"(a1), "r"(a2), "r"(a3), "r"(b0), "r"(b1));
}
__device__ __forceinline__ void ldsm4(unsigned& a0, unsigned& a1, unsigned& a2, unsigned& a3,
                                      unsigned addr) {
    asm volatile("ldmatrix.sync.aligned.m8n8.x4.shared.b16 {%0,%1,%2,%3},[%4];"
                 : "=r"(a0), "=r"(a1), "=r"(a2), "=r"(a3)
                 : "r"(addr));
}
// Pack W [K x N] row-major into m16n8k16 B-frag order, fp16 single.
__device__ __forceinline__ void frag_pack(const float* __restrict__ W, int N, int idx,
                                          int NT, uint2* dst) {
    int lane = idx & 31, nt = (idx >> 5) % NT, ks = idx / (NT * 32);
    int n = nt * 8 + (lane >> 2);
    int k0 = ks * 16 + (lane & 3) * 2;
    uint2 v;
    v.x = pack_h2(W[k0 * N + n], W[(k0 + 1) * N + n]);
    v.y = pack_h2(W[(k0 + 8) * N + n], W[(k0 + 9) * N + n]);
    dst[idx] = v;
}
// fp16 2-pass split version (hi + residual)
__device__ __forceinline__ void frag_pack2(const float* __restrict__ W, int N, int idx,
                                           int NT, uint4* dst) {
    int lane = idx & 31, nt = (idx >> 5) % NT, ks = idx / (NT * 32);
    int n = nt * 8 + (lane >> 2);
    int k0 = ks * 16 + (lane & 3) * 2;
    float w00 = W[k0 * N + n], w01 = W[(k0 + 1) * N + n];
    float w10 = W[(k0 + 8) * N + n], w11 = W[(k0 + 9) * N + n];
    __half h00 = __float2half_rn(w00), h01 = __float2half_rn(w01);
    __half h10 = __float2half_rn(w10), h11 = __float2half_rn(w11);
    uint4 v;
    {
        __half2 p0 = __halves2half2(h00, h01);
        __half2 p1 = __halves2half2(h10, h11);
        v.x = *(unsigned*)&p0;
        v.y = *(unsigned*)&p1;
    }
    v.z = pack_h2(w00 - __half2float(h00), w01 - __half2float(h01));
    v.w = pack_h2(w10 - __half2float(h10), w11 - __half2float(h11));
    dst[idx] = v;
}

// ---------------- prep kernel 1: frags, S, G ----------------
// [0,64): rc; [64,80): rm_W2; [80,96): rr; [96,112): rm_W1 2-pass; 112: S; [113,129): G
__global__ void prep_all(const float* __restrict__ rc_W, const float* __restrict__ rm_W2,
                         const float* __restrict__ rr_W, const float* __restrict__ rm_W1,
                         const float* __restrict__ fe) {
    int b = blockIdx.x, tid = threadIdx.x;
    if (b < 64) {
        frag_pack(rc_W, 256, b * 256 + tid, 32, d_Wf);
    } else if (b < 80) {
        frag_pack(rm_W2, 64, (b - 64) * 256 + tid, 8, d_W2f);
    } else if (b < 96) {
        frag_pack(rr_W, 256, (b - 80) * 256 + tid, 32, d_Wrf);
    } else if (b < 112) {
        frag_pack2(rm_W1, 256, (b - 96) * 256 + tid, 32, d_W1f);
    } else if (b == 112) {
        float s = 0.f;
#pragma unroll
        for (int k = 0; k < NF; k++) s += rm_W1[k * HID + tid];
        d_S[tid] = s;
    } else {
        int idx = (b - 113) * 256 + tid;
        int i = idx >> 6, j = idx & 63;
        const float4* a = (const float4*)(fe + i * HID);
        const float4* bp = (const float4*)(fe + j * HID);
        float s = 0.f;
#pragma unroll 8
        for (int k = 0; k < HID / 4; k++) {
            float4 x = a[k], y = bp[k];
            s = fmaf(x.x, y.x, fmaf(x.y, y.y, fmaf(x.z, y.z, fmaf(x.w, y.w, s))));
        }
        d_G[i * NF + j] = s;
    }
}

// ---------------- prep kernel 2: P = km @ rm_W1 via fp16 2-pass mma + rowsums ----------------
__global__ void __launch_bounds__(256, 2)
prep_P(const float* __restrict__ km, int nr) {
    __shared__ __align__(16) __half kmb[32 * XS];
    const int tid = threadIdx.x, w = tid >> 5, lane = tid & 31;
    const int rbase = blockIdx.x * 32;

    for (int i = tid; i < 32 * 64; i += 256) {
        int row = i >> 6, col = i & 63;
        int gr = rbase + row;
        float v = (gr < nr) ? km[(long)gr * 64 + col] : 0.f;
        kmb[row * XS + col] = __float2half_rn(v);
    }
#pragma unroll
    for (int r = 0; r < 4; r++) {
        int row = w * 4 + r, gr = rbase + row;
        int grc = (gr < nr) ? gr : (nr - 1);
        float v0 = km[(long)grc * NF + lane];
        float v1 = km[(long)grc * NF + lane + 32];
        unsigned m0 = __ballot_sync(0xffffffffu, v0 != 0.f);
        unsigned m1 = __ballot_sync(0xffffffffu, v1 != 0.f);
        if (lane == 0 && gr < nr) d_rowsum[gr] = (float)(__popc(m0) + __popc(m1));
    }
    __syncthreads();

    const int mrow0 = (w & 1) * 16, g0 = (w >> 1) * 8;
    const int arow = mrow0 + (lane >> 2);
    float acc[8][4] = {};
#pragma unroll
    for (int ks = 0; ks < 4; ks++) {
        const int acol = ks * 16 + (lane & 3) * 2;
        unsigned a0 = *(const unsigned*)(kmb + arow * XS + acol);
        unsigned a1 = *(const unsigned*)(kmb + (arow + 8) * XS + acol);
        unsigned a2 = *(const unsigned*)(kmb + arow * XS + acol + 8);
        unsigned a3 = *(const unsigned*)(kmb + (arow + 8) * XS + acol + 8);
        const uint4* Wf = d_W1f + (ks * 32 + g0) * 32 + lane;
#pragma unroll
        for (int j = 0; j < 8; j++) {
            uint4 b = Wf[j * 32];
            mma_fp16(acc[j], a0, a1, a2, a3, b.x, b.y);
            mma_fp16(acc[j], a0, a1, a2, a3, b.z, b.w);
        }
    }
    const int r0 = rbase + arow, r1 = r0 + 8;
#pragma unroll
    for (int j = 0; j < 8; j++) {
        const int col = (g0 + j) * 8 + (lane & 3) * 2;
        if (r0 < nr) *(float2*)(d_P + (long)r0 * HID + col) = make_float2(acc[j][0], acc[j][1]);
        if (r1 < nr) *(float2*)(d_P + (long)r1 * HID + col) = make_float2(acc[j][2], acc[j][3]);
    }
}

// ---------------- fused main kernel: 64 edges/CTA, 32 rows/warp ----------------
// dynamic smem: ybh [64*YS fp16]=33792, xbh @33792 [64*XS fp16]=9216,
// satv @43008 (64 int), soiv @43264 (64 int)
#define SMEM_SZ 43520

extern "C" __global__ void __launch_bounds__(256, 2)
arn_fused(const float* __restrict__ known_mask, const int* __restrict__ obs_idx,
          const int* __restrict__ obs_mask_idx, const int* __restrict__ attr_idx,
          const float* __restrict__ obs_embs,
          const float* __restrict__ rm_W1, const float* __restrict__ rm_b1,
          const float* __restrict__ rm_b2, const float* __restrict__ rr_b,
          const float* __restrict__ rc_b, float* __restrict__ out, int E) {
    extern __shared__ __align__(16) char smem[];
    __half* ybh = (__half*)smem;
    __half* xbh = (__half*)(smem + 33792);
    int* satv = (int*)(smem + 43008);
    int* soiv = (int*)(smem + 43264);

    const int w = threadIdx.x >> 5;
    const int lane = threadIdx.x & 31;
    const long bb = (long)blockIdx.x * MROWS;

    // ---- Phase AB (closed-form softmax + P table): h1 -> ybh (fp16) ----
    {
        const int row0 = w * 8;
        const int cc0 = lane * 8;
        const float E1M1 = 1.7182818284590452f;  // e - 1
#pragma unroll 1
        for (int r = 0; r < 8; r++) {
            long e = bb + row0 + r;
            long ec = (e < E) ? e : (long)(E - 1);
            int oi = obs_idx[ec];
            int omi = obs_mask_idx[ec];
            int at = attr_idx[ec];
            if (lane == 0) {
                satv[row0 + r] = at;
                soiv[row0 + r] = oi;
            }
            float t = known_mask[(long)omi * NF + at];  // 0 or 1
            float c = d_rowsum[omi] - t;
            float Z = fmaf(c, E1M1, 64.f);
            float beta = 1.f / Z;
            float dco = E1M1 * beta;
            const float* Prow = d_P + (long)omi * HID + cc0;
            float4 p0 = *(const float4*)(Prow);
            float4 p1 = *(const float4*)(Prow + 4);
            if (t != 0.f) {
                const float* w1a = rm_W1 + at * HID + cc0;
                float4 q0 = *(const float4*)(w1a);
                float4 q1 = *(const float4*)(w1a + 4);
                p0.x -= q0.x; p0.y -= q0.y; p0.z -= q0.z; p0.w -= q0.w;
                p1.x -= q1.x; p1.y -= q1.y; p1.z -= q1.z; p1.w -= q1.w;
            }
            float4 s0 = *(const float4*)(d_S + cc0);
            float4 s1 = *(const float4*)(d_S + cc0 + 4);
            float4 b0 = *(const float4*)(rm_b1 + cc0);
            float4 b1v = *(const float4*)(rm_b1 + cc0 + 4);
            float h[8];
            h[0] = gelu_fast(fmaf(beta, s0.x, fmaf(dco, p0.x, b0.x)));
            h[1] = gelu_fast(fmaf(beta, s0.y, fmaf(dco, p0.y, b0.y)));
            h[2] = gelu_fast(fmaf(beta, s0.z, fmaf(dco, p0.z, b0.z)));
            h[3] = gelu_fast(fmaf(beta, s0.w, fmaf(dco, p0.w, b0.w)));
            h[4] = gelu_fast(fmaf(beta, s1.x, fmaf(dco, p1.x, b1v.x)));
            h[5] = gelu_fast(fmaf(beta, s1.y, fmaf(dco, p1.y, b1v.y)));
            h[6] = gelu_fast(fmaf(beta, s1.z, fmaf(dco, p1.z, b1v.z)));
            h[7] = gelu_fast(fmaf(beta, s1.w, fmaf(dco, p1.w, b1v.w)));
            uint4 uh;
            uh.x = pack_h2(h[0], h[1]);
            uh.y = pack_h2(h[2], h[3]);
            uh.z = pack_h2(h[4], h[5]);
            uh.w = pack_h2(h[6], h[7]);
            *(uint4*)(ybh + (row0 + r) * YS + cc0) = uh;
        }
    }
    __syncthreads();

    const int rg = w & 1;        // 2 row groups of 32
    const int cg = w >> 1;       // 4 col groups of 64
    const int r0 = rg * 32 + (lane >> 2);  // epilogue rows: r0, r0+8, r0+16, r0+24

    // ldmatrix lane addressing for the two 16-row tiles
    const int lr = (lane & 7) + ((lane >> 3) & 1) * 8;
    const int lc = (lane >> 4) * 8;
    const unsigned ybh_s = (unsigned)__cvta_generic_to_shared(ybh);
    const unsigned xbh_s = (unsigned)__cvta_generic_to_shared(xbh);
    const unsigned ya0 = ybh_s + ((rg * 32 + lr) * YS + lc) * 2;
    const unsigned ya1 = ybh_s + ((rg * 32 + 16 + lr) * YS + lc) * 2;
    const unsigned xa0 = xbh_s + ((rg * 32 + lr) * XS + lc) * 2;
    const unsigned xa1 = xbh_s + ((rg * 32 + 16 + lr) * XS + lc) * 2;

    // ---- Phase C: mJ = gelu(h1 @ rm_W2 + b2); x = G[attr] * mJ -> xbh ----
    {
        float acc[2][2][4] = {};
#pragma unroll 1
        for (int ks = 0; ks < 16; ks++) {
            unsigned a0[4], a1[4];
            ldsm4(a0[0], a0[1], a0[2], a0[3], ya0 + ks * 32);
            ldsm4(a1[0], a1[1], a1[2], a1[3], ya1 + ks * 32);
            const uint2* Wf = d_W2f + (ks * 8 + cg * 2) * 32 + lane;
#pragma unroll
            for (int j = 0; j < 2; j++) {
                uint2 bv = Wf[j * 32];
                mma_fp16(acc[0][j], a0[0], a0[1], a0[2], a0[3], bv.x, bv.y);
                mma_fp16(acc[1][j], a1[0], a1[1], a1[2], a1[3], bv.x, bv.y);
            }
        }
#pragma unroll
        for (int t = 0; t < 2; t++) {
            const int rt = r0 + t * 16;
            const int at0 = satv[rt], at1 = satv[rt + 8];
#pragma unroll
            for (int j = 0; j < 2; j++) {
                const int col = (cg * 2 + j) * 8 + (lane & 3) * 2;
                float2 b2v = *(const float2*)(rm_b2 + col);
                float2 g0v = *(const float2*)(d_G + at0 * NF + col);
                float2 g1v = *(const float2*)(d_G + at1 * NF + col);
                *(unsigned*)(xbh + rt * XS + col) =
                    pack_h2(gelu_fast(acc[t][j][0] + b2v.x) * g0v.x,
                            gelu_fast(acc[t][j][1] + b2v.y) * g0v.y);
                *(unsigned*)(xbh + (rt + 8) * XS + col) =
                    pack_h2(gelu_fast(acc[t][j][2] + b2v.x) * g1v.x,
                            gelu_fast(acc[t][j][3] + b2v.y) * g1v.y);
            }
        }
    }
    __syncthreads();

    // ---- Phase D: a = gelu(x @ rr_W + rr_b); y = obs_h * a -> ybh ----
    {
        float acc[2][8][4] = {};
#pragma unroll
        for (int ks = 0; ks < 4; ks++) {
            unsigned a0[4], a1[4];
            ldsm4(a0[0], a0[1], a0[2], a0[3], xa0 + ks * 32);
            ldsm4(a1[0], a1[1], a1[2], a1[3], xa1 + ks * 32);
            const uint2* Wf = d_Wrf + (ks * 32 + cg * 8) * 32 + lane;
#pragma unroll
            for (int j = 0; j < 8; j++) {
                uint2 bv = Wf[j * 32];
                mma_fp16(acc[0][j], a0[0], a0[1], a0[2], a0[3], bv.x, bv.y);
                mma_fp16(acc[1][j], a1[0], a1[1], a1[2], a1[3], bv.x, bv.y);
            }
        }
#pragma unroll
        for (int t = 0; t < 2; t++) {
            const int rt = r0 + t * 16;
            const int oi0 = soiv[rt], oi1 = soiv[rt + 8];
#pragma unroll
            for (int j = 0; j < 8; j++) {
                const int col = (cg * 8 + j) * 8 + (lane & 3) * 2;
                float2 rb = *(const float2*)(rr_b + col);
                float2 h0 = *(const float2*)(obs_embs + (long)oi0 * HID + col);
                float2 h1 = *(const float2*)(obs_embs + (long)oi1 * HID + col);
                *(unsigned*)(ybh + rt * YS + col) =
                    pack_h2(gelu_fast(acc[t][j][0] + rb.x) * h0.x,
                            gelu_fast(acc[t][j][1] + rb.y) * h0.y);
                *(unsigned*)(ybh + (rt + 8) * YS + col) =
                    pack_h2(gelu_fast(acc[t][j][2] + rb.x) * h1.x,
                            gelu_fast(acc[t][j][3] + rb.y) * h1.y);
            }
        }
    }
    __syncthreads();

    // ---- Phase E: out = gelu(y @ rc_W + rc_b)  (exact gelu) ----
    {
        float acc[2][8][4] = {};
#pragma unroll 1
        for (int ks = 0; ks < 16; ks++) {
            unsigned a0[4], a1[4];
            ldsm4(a0[0], a0[1], a0[2], a0[3], ya0 + ks * 32);
            ldsm4(a1[0], a1[1], a1[2], a1[3], ya1 + ks * 32);
            const uint2* Wf = d_Wf + (ks * 32 + cg * 8) * 32 + lane;
#pragma unroll
            for (int j = 0; j < 8; j++) {
                uint2 bv = Wf[j * 32];
                mma_fp16(acc[0][j], a0[0], a0[1], a0[2], a0[3], bv.x, bv.y);
                mma_fp16(acc[1][j], a1[0], a1[1], a1[2], a1[3], bv.x, bv.y);
            }
        }
#pragma unroll
        for (int t = 0; t < 2; t++) {
            const int rt = r0 + t * 16;
            const long e0 = bb + rt, e1 = e0 + 8;
            const bool w0 = (e0 < (long)E), w1 = (e1 < (long)E);
#pragma unroll
            for (int j = 0; j < 8; j++) {
                const int col = (cg * 8 + j) * 8 + (lane & 3) * 2;
                float2 bv = *(const float2*)(rc_b + col);
                if (w0) {
                    float2 o;
                    o.x = gelu_exact(acc[t][j][0] + bv.x);
                    o.y = gelu_exact(acc[t][j][1] + bv.y);
                    *(float2*)(out + e0 * HID + col) = o;
                }
                if (w1) {
                    float2 o;
                    o.x = gelu_exact(acc[t][j][2] + bv.x);
                    o.y = gelu_exact(acc[t][j][3] + bv.y);
                    *(float2*)(out + e1 * HID + col) = o;
                }
            }
        }
    }
}

// ---------------- launch ----------------
extern "C" void kernel_launch(void* const* d_in, const int* in_sizes, int n_in,
                              void* d_out, int out_size) {
    const float* known_mask = (const float*)d_in[0];
    const int* obs_idx = (const int*)d_in[1];
    const int* obs_mask_idx = (const int*)d_in[2];
    const int* attr_idx = (const int*)d_in[3];
    const float* obs_embs = (const float*)d_in[4];
    const float* feature_emb = (const float*)d_in[5];
    const float* rm_W1 = (const float*)d_in[6];
    const float* rm_b1 = (const float*)d_in[7];
    const float* rm_W2 = (const float*)d_in[8];
    const float* rm_b2 = (const float*)d_in[9];
    const float* rr_W = (const float*)d_in[10];
    const float* rr_b = (const float*)d_in[11];
    const float* rc_W = (const float*)d_in[12];
    const float* rc_b = (const float*)d_in[13];
    int E = in_sizes[1];
    int nr = in_sizes[0] / NF;

    static bool attr_set = false;
    if (!attr_set) {
        cudaFuncSetAttribute(arn_fused, cudaFuncAttributeMaxDynamicSharedMemorySize, SMEM_SZ);
        attr_set = true;
    }

    prep_all<<<129, 256>>>(rc_W, rm_W2, rr_W, rm_W1, feature_emb);
    prep_P<<<(nr + 31) / 32, 256>>>(known_mask, nr);
    int grid = (E + MROWS - 1) / MROWS;
    arn_fused<<<grid, 256, SMEM_SZ>>>(known_mask, obs_idx, obs_mask_idx, attr_idx, obs_embs,
                                      rm_W1, rm_b1, rm_b2, rr_b, rc_b, (float*)d_out, E);
}

// round 12
// speedup vs baseline: 1.8208x; 1.0840x over previous
#include <cuda_runtime.h>
#include <cuda_fp16.h>
#include <math.h>

#define HID 256
#define NF  64
#define YS  264   // fp16 row stride, 256-col tiles
#define XS  72    // fp16 row stride, 64-col tiles
#define NRMAX 100352
#define MROWS 64  // edges per CTA

// ---------------- device scratch ----------------
__device__ float d_G[NF * NF];
__device__ __half d_P[(size_t)NRMAX * HID];  // known_mask @ rm_W1 (fp16)
__device__ float d_rowsum[NRMAX];
__device__ float d_S[HID];  // colsum(rm_W1)
// fp16 fragment tables
__device__ uint2 d_Wf[16 * 32 * 32];   // rc_W  (128KB, L1-resident)
__device__ uint2 d_W2f[16 * 8 * 32];   // rm_W2
__device__ uint2 d_Wrf[4 * 32 * 32];   // rr_W
__device__ uint4 d_W1f[4 * 32 * 32];   // rm_W1 2-pass {h0,h1,l0,l1} (for P prep)

// ---------------- helpers ----------------
__device__ __forceinline__ float gelu_fast(float x) {
    float inner = 0.7978845608028654f * x * fmaf(0.044715f, x * x, 1.f);
    float t;
    asm("tanh.approx.f32 %0,%1;" : "=f"(t) : "f"(inner));
    return 0.5f * x * (1.f + t);
}
__device__ __forceinline__ unsigned pack_h2(float x, float y) {
    __half2 h = __floats2half2_rn(x, y);
    return *(unsigned*)&h;
}
// packed half2 gelu (tanh approx) on 2 fp16 values
__device__ __forceinline__ unsigned gelu_h2(unsigned xin) {
    __half2 x = *(__half2*)&xin;
    __half2 s = __hmul2(x, x);
    const __half2 c1 = __floats2half2_rn(0.0356774081f, 0.0356774081f);
    const __half2 c0 = __floats2half2_rn(0.7978845608f, 0.7978845608f);
    __half2 inner = __hmul2(x, __hfma2(s, c1, c0));
    unsigned t;
    asm("tanh.approx.f16x2 %0,%1;" : "=r"(t) : "r"(*(unsigned*)&inner));
    __half2 th = *(__half2*)&t;
    const __half2 one = __floats2half2_rn(1.f, 1.f);
    const __half2 half_ = __floats2half2_rn(0.5f, 0.5f);
    __half2 res = __hmul2(__hmul2(x, half_), __hadd2(th, one));
    return *(unsigned*)&res;
}
__device__ __forceinline__ unsigned hmul2u(unsigned a, unsigned b) {
    __half2 r = __hmul2(*(__half2*)&a, *(__half2*)&b);
    return *(unsigned*)&r;
}
__device__ __forceinline__ void mma_fp16(float c[4], unsigned a0, unsigned a1, unsigned a2,
                                         unsigned a3, unsigned b0, unsigned b1) {
    asm("mma.sync.aligned.m16n8k16.row.col.f32.f16.f16.f32 "
        "{%0,%1,%2,%3},{%4,%5,%6,%7},{%8,%9},{%0,%1,%2,%3};"
        : "+f"(c[0]), "+f"(c[1]), "+f"(c[2]), "+f"(c[3])
        : "r"(a0), "r"(a1), "r"(a2), "r"(a3), "r"(b0), "r"(b1));
}
__device__ __forceinline__ void ldsm4(unsigned& a0, unsigned& a1, unsigned& a2, unsigned& a3,
                                      unsigned addr) {
    asm volatile("ldmatrix.sync.aligned.m8n8.x4.shared.b16 {%0,%1,%2,%3},[%4];"
                 : "=r"(a0), "=r"(a1), "=r"(a2), "=r"(a3)
                 : "r"(addr));
}
__device__ __forceinline__ void frag_pack(const float* __restrict__ W, int N, int idx,
                                          int NT, uint2* dst) {
    int lane = idx & 31, nt = (idx >> 5) % NT, ks = idx / (NT * 32);
    int n = nt * 8 + (lane >> 2);
    int k0 = ks * 16 + (lane & 3) * 2;
    uint2 v;
    v.x = pack_h2(W[k0 * N + n], W[(k0 + 1) * N + n]);
    v.y = pack_h2(W[(k0 + 8) * N + n], W[(k0 + 9) * N + n]);
    dst[idx] = v;
}
__device__ __forceinline__ void frag_pack2(const float* __restrict__ W, int N, int idx,
                                           int NT, uint4* dst) {
    int lane = idx & 31, nt = (idx >> 5) % NT, ks = idx / (NT * 32);
    int n = nt * 8 + (lane >> 2);
    int k0 = ks * 16 + (lane & 3) * 2;
    float w00 = W[k0 * N + n], w01 = W[(k0 + 1) * N + n];
    float w10 = W[(k0 + 8) * N + n], w11 = W[(k0 + 9) * N + n];
    __half h00 = __float2half_rn(w00), h01 = __float2half_rn(w01);
    __half h10 = __float2half_rn(w10), h11 = __float2half_rn(w11);
    uint4 v;
    {
        __half2 p0 = __halves2half2(h00, h01);
        __half2 p1 = __halves2half2(h10, h11);
        v.x = *(unsigned*)&p0;
        v.y = *(unsigned*)&p1;
    }
    v.z = pack_h2(w00 - __half2float(h00), w01 - __half2float(h01));
    v.w = pack_h2(w10 - __half2float(h10), w11 - __half2float(h11));
    dst[idx] = v;
}

// ---------------- prep kernel 1: frags, S, G ----------------
__global__ void prep_all(const float* __restrict__ rc_W, const float* __restrict__ rm_W2,
                         const float* __restrict__ rr_W, const float* __restrict__ rm_W1,
                         const float* __restrict__ fe) {
    int b = blockIdx.x, tid = threadIdx.x;
    if (b < 64) {
        frag_pack(rc_W, 256, b * 256 + tid, 32, d_Wf);
    } else if (b < 80) {
        frag_pack(rm_W2, 64, (b - 64) * 256 + tid, 8, d_W2f);
    } else if (b < 96) {
        frag_pack(rr_W, 256, (b - 80) * 256 + tid, 32, d_Wrf);
    } else if (b < 112) {
        frag_pack2(rm_W1, 256, (b - 96) * 256 + tid, 32, d_W1f);
    } else if (b == 112) {
        float s = 0.f;
#pragma unroll
        for (int k = 0; k < NF; k++) s += rm_W1[k * HID + tid];
        d_S[tid] = s;
    } else {
        int idx = (b - 113) * 256 + tid;
        int i = idx >> 6, j = idx & 63;
        const float4* a = (const float4*)(fe + i * HID);
        const float4* bp = (const float4*)(fe + j * HID);
        float s = 0.f;
#pragma unroll 8
        for (int k = 0; k < HID / 4; k++) {
            float4 x = a[k], y = bp[k];
            s = fmaf(x.x, y.x, fmaf(x.y, y.y, fmaf(x.z, y.z, fmaf(x.w, y.w, s))));
        }
        d_G[i * NF + j] = s;
    }
}

// ---------------- prep kernel 2: P = km @ rm_W1 (fp16 2-pass mma) + rowsums ----------------
__global__ void __launch_bounds__(256, 2)
prep_P(const float* __restrict__ km, int nr) {
    __shared__ __align__(16) __half kmb[32 * XS];
    const int tid = threadIdx.x, w = tid >> 5, lane = tid & 31;
    const int rbase = blockIdx.x * 32;

    for (int i = tid; i < 32 * 64; i += 256) {
        int row = i >> 6, col = i & 63;
        int gr = rbase + row;
        float v = (gr < nr) ? km[(long)gr * 64 + col] : 0.f;
        kmb[row * XS + col] = __float2half_rn(v);
    }
#pragma unroll
    for (int r = 0; r < 4; r++) {
        int row = w * 4 + r, gr = rbase + row;
        int grc = (gr < nr) ? gr : (nr - 1);
        float v0 = km[(long)grc * NF + lane];
        float v1 = km[(long)grc * NF + lane + 32];
        unsigned m0 = __ballot_sync(0xffffffffu, v0 != 0.f);
        unsigned m1 = __ballot_sync(0xffffffffu, v1 != 0.f);
        if (lane == 0 && gr < nr) d_rowsum[gr] = (float)(__popc(m0) + __popc(m1));
    }
    __syncthreads();

    const int mrow0 = (w & 1) * 16, g0 = (w >> 1) * 8;
    const int arow = mrow0 + (lane >> 2);
    float acc[8][4] = {};
#pragma unroll
    for (int ks = 0; ks < 4; ks++) {
        const int acol = ks * 16 + (lane & 3) * 2;
        unsigned a0 = *(const unsigned*)(kmb + arow * XS + acol);
        unsigned a1 = *(const unsigned*)(kmb + (arow + 8) * XS + acol);
        unsigned a2 = *(const unsigned*)(kmb + arow * XS + acol + 8);
        unsigned a3 = *(const unsigned*)(kmb + (arow + 8) * XS + acol + 8);
        const uint4* Wf = d_W1f + (ks * 32 + g0) * 32 + lane;
#pragma unroll
        for (int j = 0; j < 8; j++) {
            uint4 b = Wf[j * 32];
            mma_fp16(acc[j], a0, a1, a2, a3, b.x, b.y);
            mma_fp16(acc[j], a0, a1, a2, a3, b.z, b.w);
        }
    }
    const int r0 = rbase + arow, r1 = r0 + 8;
#pragma unroll
    for (int j = 0; j < 8; j++) {
        const int col = (g0 + j) * 8 + (lane & 3) * 2;
        if (r0 < nr) *(unsigned*)(d_P + (long)r0 * HID + col) = pack_h2(acc[j][0], acc[j][1]);
        if (r1 < nr) *(unsigned*)(d_P + (long)r1 * HID + col) = pack_h2(acc[j][2], acc[j][3]);
    }
}

// ---------------- fused main kernel: 64 edges/CTA, 32 rows/warp ----------------
#define SMEM_SZ 43520

extern "C" __global__ void __launch_bounds__(256, 2)
arn_fused(const float* __restrict__ known_mask, const int* __restrict__ obs_idx,
          const int* __restrict__ obs_mask_idx, const int* __restrict__ attr_idx,
          const float* __restrict__ obs_embs,
          const float* __restrict__ rm_W1, const float* __restrict__ rm_b1,
          const float* __restrict__ rm_b2, const float* __restrict__ rr_b,
          const float* __restrict__ rc_b, float* __restrict__ out, int E) {
    extern __shared__ __align__(16) char smem[];
    __half* ybh = (__half*)smem;
    __half* xbh = (__half*)(smem + 33792);
    int* satv = (int*)(smem + 43008);
    int* soiv = (int*)(smem + 43264);

    const int w = threadIdx.x >> 5;
    const int lane = threadIdx.x & 31;
    const long bb = (long)blockIdx.x * MROWS;

    // ---- Phase AB (closed-form softmax + fp16 P table): h1 -> ybh ----
    {
        const int row0 = w * 8;
        const int cc0 = lane * 8;
        const float E1M1 = 1.7182818284590452f;  // e - 1
#pragma unroll 1
        for (int r = 0; r < 8; r++) {
            long e = bb + row0 + r;
            long ec = (e < E) ? e : (long)(E - 1);
            int oi = obs_idx[ec];
            int omi = obs_mask_idx[ec];
            int at = attr_idx[ec];
            if (lane == 0) {
                satv[row0 + r] = at;
                soiv[row0 + r] = oi;
            }
            float t = known_mask[(long)omi * NF + at];  // 0 or 1
            float c = d_rowsum[omi] - t;
            float Z = fmaf(c, E1M1, 64.f);
            float beta = 1.f / Z;
            float dco = E1M1 * beta;
            uint4 pu = *(const uint4*)(d_P + (long)omi * HID + cc0);
            float2 pa = __half22float2(*(__half2*)&pu.x);
            float2 pb = __half22float2(*(__half2*)&pu.y);
            float2 pc = __half22float2(*(__half2*)&pu.z);
            float2 pd = __half22float2(*(__half2*)&pu.w);
            float p[8] = {pa.x, pa.y, pb.x, pb.y, pc.x, pc.y, pd.x, pd.y};
            if (t != 0.f) {
                const float* w1a = rm_W1 + at * HID + cc0;
                float4 q0 = *(const float4*)(w1a);
                float4 q1 = *(const float4*)(w1a + 4);
                p[0] -= q0.x; p[1] -= q0.y; p[2] -= q0.z; p[3] -= q0.w;
                p[4] -= q1.x; p[5] -= q1.y; p[6] -= q1.z; p[7] -= q1.w;
            }
            float4 s0 = *(const float4*)(d_S + cc0);
            float4 s1 = *(const float4*)(d_S + cc0 + 4);
            float4 b0 = *(const float4*)(rm_b1 + cc0);
            float4 b1v = *(const float4*)(rm_b1 + cc0 + 4);
            float pre[8];
            pre[0] = fmaf(beta, s0.x, fmaf(dco, p[0], b0.x));
            pre[1] = fmaf(beta, s0.y, fmaf(dco, p[1], b0.y));
            pre[2] = fmaf(beta, s0.z, fmaf(dco, p[2], b0.z));
            pre[3] = fmaf(beta, s0.w, fmaf(dco, p[3], b0.w));
            pre[4] = fmaf(beta, s1.x, fmaf(dco, p[4], b1v.x));
            pre[5] = fmaf(beta, s1.y, fmaf(dco, p[5], b1v.y));
            pre[6] = fmaf(beta, s1.z, fmaf(dco, p[6], b1v.z));
            pre[7] = fmaf(beta, s1.w, fmaf(dco, p[7], b1v.w));
            uint4 uh;
            uh.x = gelu_h2(pack_h2(pre[0], pre[1]));
            uh.y = gelu_h2(pack_h2(pre[2], pre[3]));
            uh.z = gelu_h2(pack_h2(pre[4], pre[5]));
            uh.w = gelu_h2(pack_h2(pre[6], pre[7]));
            *(uint4*)(ybh + (row0 + r) * YS + cc0) = uh;
        }
    }
    __syncthreads();

    const int rg = w & 1;   // 2 row groups of 32
    const int cg = w >> 1;  // 4 col groups of 64
    const int r0 = rg * 32 + (lane >> 2);

    const int lr = (lane & 7) + ((lane >> 3) & 1) * 8;
    const int lc = (lane >> 4) * 8;
    const unsigned ybh_s = (unsigned)__cvta_generic_to_shared(ybh);
    const unsigned xbh_s = (unsigned)__cvta_generic_to_shared(xbh);
    const unsigned ya0 = ybh_s + ((rg * 32 + lr) * YS + lc) * 2;
    const unsigned ya1 = ybh_s + ((rg * 32 + 16 + lr) * YS + lc) * 2;
    const unsigned xa0 = xbh_s + ((rg * 32 + lr) * XS + lc) * 2;
    const unsigned xa1 = xbh_s + ((rg * 32 + 16 + lr) * XS + lc) * 2;

    // ---- Phase C: mJ = gelu(h1 @ rm_W2 + b2); x = G[attr] * mJ -> xbh ----
    {
        float acc[2][2][4] = {};
#pragma unroll 1
        for (int ks = 0; ks < 16; ks++) {
            unsigned a0[4], a1[4];
            ldsm4(a0[0], a0[1], a0[2], a0[3], ya0 + ks * 32);
            ldsm4(a1[0], a1[1], a1[2], a1[3], ya1 + ks * 32);
            const uint2* Wf = d_W2f + (ks * 8 + cg * 2) * 32 + lane;
#pragma unroll
            for (int j = 0; j < 2; j++) {
                uint2 bv = Wf[j * 32];
                mma_fp16(acc[0][j], a0[0], a0[1], a0[2], a0[3], bv.x, bv.y);
                mma_fp16(acc[1][j], a1[0], a1[1], a1[2], a1[3], bv.x, bv.y);
            }
        }
#pragma unroll
        for (int t = 0; t < 2; t++) {
            const int rt = r0 + t * 16;
            const int at0 = satv[rt], at1 = satv[rt + 8];
#pragma unroll
            for (int j = 0; j < 2; j++) {
                const int col = (cg * 2 + j) * 8 + (lane & 3) * 2;
                float2 b2v = *(const float2*)(rm_b2 + col);
                float2 g0v = *(const float2*)(d_G + at0 * NF + col);
                float2 g1v = *(const float2*)(d_G + at1 * NF + col);
                *(unsigned*)(xbh + rt * XS + col) =
                    hmul2u(gelu_h2(pack_h2(acc[t][j][0] + b2v.x, acc[t][j][1] + b2v.y)),
                           pack_h2(g0v.x, g0v.y));
                *(unsigned*)(xbh + (rt + 8) * XS + col) =
                    hmul2u(gelu_h2(pack_h2(acc[t][j][2] + b2v.x, acc[t][j][3] + b2v.y)),
                           pack_h2(g1v.x, g1v.y));
            }
        }
    }
    __syncthreads();

    // ---- Phase D: a = gelu(x @ rr_W + rr_b); y = obs_h * a -> ybh ----
    {
        float acc[2][8][4] = {};
#pragma unroll
        for (int ks = 0; ks < 4; ks++) {
            unsigned a0[4], a1[4];
            ldsm4(a0[0], a0[1], a0[2], a0[3], xa0 + ks * 32);
            ldsm4(a1[0], a1[1], a1[2], a1[3], xa1 + ks * 32);
            const uint2* Wf = d_Wrf + (ks * 32 + cg * 8) * 32 + lane;
#pragma unroll
            for (int j = 0; j < 8; j++) {
                uint2 bv = Wf[j * 32];
                mma_fp16(acc[0][j], a0[0], a0[1], a0[2], a0[3], bv.x, bv.y);
                mma_fp16(acc[1][j], a1[0], a1[1], a1[2], a1[3], bv.x, bv.y);
            }
        }
#pragma unroll
        for (int t = 0; t < 2; t++) {
            const int rt = r0 + t * 16;
            const int oi0 = soiv[rt], oi1 = soiv[rt + 8];
#pragma unroll
            for (int j = 0; j < 8; j++) {
                const int col = (cg * 8 + j) * 8 + (lane & 3) * 2;
                float2 rb = *(const float2*)(rr_b + col);
                float2 h0 = *(const float2*)(obs_embs + (long)oi0 * HID + col);
                float2 h1 = *(const float2*)(obs_embs + (long)oi1 * HID + col);
                *(unsigned*)(ybh + rt * YS + col) =
                    hmul2u(gelu_h2(pack_h2(acc[t][j][0] + rb.x, acc[t][j][1] + rb.y)),
                           pack_h2(h0.x, h0.y));
                *(unsigned*)(ybh + (rt + 8) * YS + col) =
                    hmul2u(gelu_h2(pack_h2(acc[t][j][2] + rb.x, acc[t][j][3] + rb.y)),
                           pack_h2(h1.x, h1.y));
            }
        }
    }
    __syncthreads();

    // ---- Phase E: out = gelu(y @ rc_W + rc_b)  (fp32 tanh gelu) ----
    {
        float acc[2][8][4] = {};
#pragma unroll 1
        for (int ks = 0; ks < 16; ks++) {
            unsigned a0[4], a1[4];
            ldsm4(a0[0], a0[1], a0[2], a0[3], ya0 + ks * 32);
            ldsm4(a1[0], a1[1], a1[2], a1[3], ya1 + ks * 32);
            const uint2* Wf = d_Wf + (ks * 32 + cg * 8) * 32 + lane;
#pragma unroll
            for (int j = 0; j < 8; j++) {
                uint2 bv = Wf[j * 32];
                mma_fp16(acc[0][j], a0[0], a0[1], a0[2], a0[3], bv.x, bv.y);
                mma_fp16(acc[1][j], a1[0], a1[1], a1[2], a1[3], bv.x, bv.y);
            }
        }
#pragma unroll
        for (int t = 0; t < 2; t++) {
            const int rt = r0 + t * 16;
            const long e0 = bb + rt, e1 = e0 + 8;
            const bool w0 = (e0 < (long)E), w1 = (e1 < (long)E);
#pragma unroll
            for (int j = 0; j < 8; j++) {
                const int col = (cg * 8 + j) * 8 + (lane & 3) * 2;
                float2 bv = *(const float2*)(rc_b + col);
                if (w0) {
                    float2 o;
                    o.x = gelu_fast(acc[t][j][0] + bv.x);
                    o.y = gelu_fast(acc[t][j][1] + bv.y);
                    *(float2*)(out + e0 * HID + col) = o;
                }
                if (w1) {
                    float2 o;
                    o.x = gelu_fast(acc[t][j][2] + bv.x);
                    o.y = gelu_fast(acc[t][j][3] + bv.y);
                    *(float2*)(out + e1 * HID + col) = o;
                }
            }
        }
    }
}

// ---------------- launch ----------------
extern "C" void kernel_launch(void* const* d_in, const int* in_sizes, int n_in,
                              void* d_out, int out_size) {
    const float* known_mask = (const float*)d_in[0];
    const int* obs_idx = (const int*)d_in[1];
    const int* obs_mask_idx = (const int*)d_in[2];
    const int* attr_idx = (const int*)d_in[3];
    const float* obs_embs = (const float*)d_in[4];
    const float* feature_emb = (const float*)d_in[5];
    const float* rm_W1 = (const float*)d_in[6];
    const float* rm_b1 = (const float*)d_in[7];
    const float* rm_W2 = (const float*)d_in[8];
    const float* rm_b2 = (const float*)d_in[9];
    const float* rr_W = (const float*)d_in[10];
    const float* rr_b = (const float*)d_in[11];
    const float* rc_W = (const float*)d_in[12];
    const float* rc_b = (const float*)d_in[13];
    int E = in_sizes[1];
    int nr = in_sizes[0] / NF;

    static bool attr_set = false;
    if (!attr_set) {
        cudaFuncSetAttribute(arn_fused, cudaFuncAttributeMaxDynamicSharedMemorySize, SMEM_SZ);
        attr_set = true;
    }

    prep_all<<<129, 256>>>(rc_W, rm_W2, rr_W, rm_W1, feature_emb);
    prep_P<<<(nr + 31) / 32, 256>>>(known_mask, nr);
    int grid = (E + MROWS - 1) / MROWS;
    arn_fused<<<grid, 256, SMEM_SZ>>>(known_mask, obs_idx, obs_mask_idx, attr_idx, obs_embs,
                                      rm_W1, rm_b1, rm_b2, rr_b, rc_b, (float*)d_out, E);
}